// round 9
// baseline (speedup 1.0000x reference)
#include <cuda_runtime.h>
#include <cuda_bf16.h>
#include <cuda_fp16.h>
#include <cstdint>
#include <math.h>

#define Bc 4
#define Sc 1024
#define Dm 1024
#define Hc 16
#define Dk 64

// -------- device scratch (allocation-free: static device globals) --------
__device__ float g_X[Bc * Sc * Dm];        // pre-LN activations

// bf16 split scratch
__device__ __align__(256) unsigned short g_mh[4194304], g_ml[4194304];   // memory hi/lo
__device__ __align__(256) unsigned short g_dh[4194304], g_dl[4194304];   // decoder hi/lo
__device__ __align__(256) unsigned short g_ch[4194304], g_cl[4194304];   // ctx hi/lo
__device__ __align__(256) unsigned short g_WqTh[1048576], g_WqTl[1048576];
__device__ __align__(256) unsigned short g_WkTh[1048576], g_WkTl[1048576];
__device__ __align__(256) unsigned short g_WvTh[1048576], g_WvTl[1048576];
__device__ __align__(256) unsigned short g_WoTh[1048576], g_WoTl[1048576];
// attention operands
__device__ __align__(256) unsigned short g_Qh[4194304], g_Ql[4194304];   // [b,h,s,d] bf16
__device__ __align__(256) unsigned short g_Kh[4194304], g_Kl[4194304];   // [b,h,s,d] bf16
__device__ __align__(256) __half g_VT[4194304];                          // [b,h,d,s] fp16

// ======================== PTX helpers (base sm_80+ ISA only) ==============
__device__ __forceinline__ uint32_t smem_to_u32(const void* p) {
    uint32_t a;
    asm("{ .reg .u64 t; cvta.to.shared.u64 t, %1; cvt.u32.u64 %0, t; }"
        : "=r"(a) : "l"(p));
    return a;
}

#define CP_ASYNC16(sm, gp) \
    asm volatile("cp.async.cg.shared.global [%0], [%1], 16;" \
        :: "r"(sm), "l"(gp) : "memory")
#define CP_COMMIT() asm volatile("cp.async.commit_group;" ::: "memory")
#define CP_WAIT0()  asm volatile("cp.async.wait_group 0;" ::: "memory")

#define LDMATRIX_X4(r0, r1, r2, r3, addr) \
    asm volatile("ldmatrix.sync.aligned.m8n8.x4.shared.b16 {%0,%1,%2,%3}, [%4];" \
        : "=r"(r0), "=r"(r1), "=r"(r2), "=r"(r3) : "r"(addr))

#define MMA16816(C, A, B) \
    asm volatile("mma.sync.aligned.m16n8k16.row.col.f32.bf16.bf16.f32 " \
        "{%0,%1,%2,%3}, {%4,%5,%6,%7}, {%8,%9}, {%0,%1,%2,%3};" \
        : "+f"((C)[0]), "+f"((C)[1]), "+f"((C)[2]), "+f"((C)[3]) \
        : "r"((A)[0]), "r"((A)[1]), "r"((A)[2]), "r"((A)[3]), \
          "r"((B)[0]), "r"((B)[1]))

#define MMA16816F16(C, A, B) \
    asm volatile("mma.sync.aligned.m16n8k16.row.col.f32.f16.f16.f32 " \
        "{%0,%1,%2,%3}, {%4,%5,%6,%7}, {%8,%9}, {%0,%1,%2,%3};" \
        : "+f"((C)[0]), "+f"((C)[1]), "+f"((C)[2]), "+f"((C)[3]) \
        : "r"((A)[0]), "r"((A)[1]), "r"((A)[2]), "r"((A)[3]), \
          "r"((B)[0]), "r"((B)[1]))

// ===========================================================================
// split2: fp32 -> bf16 hi + lo, two sources batched via blockIdx.y
// ===========================================================================
struct SplitArgs {
    const float* src[2];
    unsigned short* hi[2];
    unsigned short* lo[2];
};
__global__ __launch_bounds__(256) void split2_kernel(SplitArgs a, int n4)
{
    const int w = blockIdx.y;
    int i = blockIdx.x * 256 + threadIdx.x;
    if (i >= n4) return;
    float4 v = ((const float4*)a.src[w])[i];
    float f[4] = {v.x, v.y, v.z, v.w};
#pragma unroll
    for (int j = 0; j < 4; j++) {
        __nv_bfloat16 h = __float2bfloat16_rn(f[j]);
        __nv_bfloat16 l = __float2bfloat16_rn(f[j] - __bfloat162float(h));
        a.hi[w][i * 4 + j] = __bfloat16_as_ushort(h);
        a.lo[w][i * 4 + j] = __bfloat16_as_ushort(l);
    }
}

// ===========================================================================
// transsplit4: W[k][n] fp32 -> WT_hi[n][k], WT_lo[n][k] bf16, 4 weights (z)
// ===========================================================================
struct TSArgs {
    const float* W[4];
    unsigned short* hi[4];
    unsigned short* lo[4];
};
__global__ __launch_bounds__(256) void transsplit4_kernel(TSArgs a)
{
    __shared__ unsigned short sh[64][68];
    __shared__ unsigned short sl[64][68];
    const int w = blockIdx.z;
    const float* W = a.W[w];
    const int k0 = blockIdx.y << 6, n0 = blockIdx.x << 6;
    const int r = threadIdx.x >> 4, c = (threadIdx.x & 15) << 2;
#pragma unroll
    for (int it = 0; it < 4; it++) {
        int row = r + it * 16;
        float4 v = *(const float4*)&W[(size_t)(k0 + row) * 1024 + n0 + c];
        float f[4] = {v.x, v.y, v.z, v.w};
#pragma unroll
        for (int j = 0; j < 4; j++) {
            __nv_bfloat16 h = __float2bfloat16_rn(f[j]);
            __nv_bfloat16 l = __float2bfloat16_rn(f[j] - __bfloat162float(h));
            sh[row][c + j] = __bfloat16_as_ushort(h);
            sl[row][c + j] = __bfloat16_as_ushort(l);
        }
    }
    __syncthreads();
#pragma unroll
    for (int it = 0; it < 4; it++) {
        int nn = r + it * 16;
#pragma unroll
        for (int j = 0; j < 4; j++) {
            a.hi[w][(size_t)(n0 + nn) * 1024 + k0 + c + j] = sh[c + j][nn];
            a.lo[w][(size_t)(n0 + nn) * 1024 + k0 + c + j] = sl[c + j][nn];
        }
    }
}

// ===========================================================================
// HMMA GEMM (bf16 3-product split), 128x128 tile, BK=64, double-buffered.
// R6 known-good: 256 threads, warp grid 4(M) x 2(N), warp tile 32x64.
// MODE 0: Q/K proj -> bf16 hi/lo scatter [b,h,s,d], (acc+bias)*scale
// MODE 1: out proj -> fp32 row-major, acc + bias + residual
// MODE 2: V proj -> fp16 transposed [b,h,d,s], acc + bias
// ===========================================================================
#define GT_ROW   72
#define GT_TILEB (128 * GT_ROW * 2)    // 18432
#define GT_STAGEB (4 * GT_TILEB)       // 73728
#define GT_SMEM_SZ (2 * GT_STAGEB)     // 147456

template <int MODE>
__global__ __launch_bounds__(256, 1)
void gemm_mma(const unsigned short* __restrict__ Ah, const unsigned short* __restrict__ Al,
              const unsigned short* __restrict__ Bh, const unsigned short* __restrict__ Bl,
              const float* __restrict__ bias, const float* __restrict__ residual,
              void* __restrict__ C0, void* __restrict__ C1, float scale)
{
    extern __shared__ char smem[];
    const uint32_t sb = smem_to_u32(smem);
    const int tid = threadIdx.x;
    const int wid = tid >> 5, lane = tid & 31;
    const int wm = wid & 3, wn = wid >> 2;
    const int m0 = blockIdx.y * 128, n0 = blockIdx.x * 128;

    const int crow = tid >> 1;
    const int cseg = (tid & 1) * 4;
    const unsigned short* gsrc[4] = {
        Ah + (size_t)(m0 + crow) * 1024, Al + (size_t)(m0 + crow) * 1024,
        Bh + (size_t)(n0 + crow) * 1024, Bl + (size_t)(n0 + crow) * 1024};
    const uint32_t srow = crow * (GT_ROW * 2) + cseg * 16;

    auto load_stage = [&](int stg, int k0) {
#pragma unroll
        for (int tile = 0; tile < 4; tile++) {
            const unsigned short* g = gsrc[tile] + k0 + cseg * 8;
            uint32_t s = sb + stg * GT_STAGEB + tile * GT_TILEB + srow;
#pragma unroll
            for (int i = 0; i < 4; i++)
                CP_ASYNC16(s + i * 16, g + i * 8);
        }
        CP_COMMIT();
    };

    float acc[2][8][4];
#pragma unroll
    for (int mt = 0; mt < 2; mt++)
#pragma unroll
        for (int nt = 0; nt < 8; nt++)
#pragma unroll
            for (int j = 0; j < 4; j++) acc[mt][nt][j] = 0.f;

    const int lg = lane >> 3, lr = lane & 7;
    const int rowoff = (lg & 1) * 8 + lr;
    const uint32_t kquad = (lg >> 1) * 16;

    load_stage(0, 0);
    CP_WAIT0();
    __syncthreads();

    for (int t = 0; t < 16; t++) {
        const int buf = t & 1;
        if (t + 1 < 16) load_stage(buf ^ 1, (t + 1) * 64);

        const uint32_t stg = sb + buf * GT_STAGEB;
#pragma unroll
        for (int ks = 0; ks < 4; ks++) {
            const uint32_t kb = ks * 32 + kquad;
            uint32_t ah[2][4], al[2][4];
#pragma unroll
            for (int mt = 0; mt < 2; mt++) {
                uint32_t r = (wm * 32 + mt * 16 + rowoff) * (GT_ROW * 2) + kb;
                LDMATRIX_X4(ah[mt][0], ah[mt][1], ah[mt][2], ah[mt][3], stg + r);
                LDMATRIX_X4(al[mt][0], al[mt][1], al[mt][2], al[mt][3],
                            stg + GT_TILEB + r);
            }
            uint32_t bh[8][2], bl[8][2];
#pragma unroll
            for (int p = 0; p < 4; p++) {
                uint32_t r = (wn * 64 + p * 16 + rowoff) * (GT_ROW * 2) + kb;
                LDMATRIX_X4(bh[2 * p][0], bh[2 * p + 1][0],
                            bh[2 * p][1], bh[2 * p + 1][1],
                            stg + 2 * GT_TILEB + r);
                LDMATRIX_X4(bl[2 * p][0], bl[2 * p + 1][0],
                            bl[2 * p][1], bl[2 * p + 1][1],
                            stg + 3 * GT_TILEB + r);
            }
#pragma unroll
            for (int mt = 0; mt < 2; mt++)
#pragma unroll
                for (int nt = 0; nt < 8; nt++) {
                    MMA16816(acc[mt][nt], ah[mt], bh[nt]);
                    MMA16816(acc[mt][nt], ah[mt], bl[nt]);
                    MMA16816(acc[mt][nt], al[mt], bh[nt]);
                }
        }
        if (t + 1 < 16) CP_WAIT0();
        __syncthreads();
    }

    // ---- epilogue ----
    const int erow = lane >> 2;
    const int ecol = (lane & 3) * 2;
#pragma unroll
    for (int mt = 0; mt < 2; mt++) {
#pragma unroll
        for (int nt = 0; nt < 8; nt++) {
            const int n = n0 + wn * 64 + nt * 8 + ecol;
            const float b0 = bias[n], b1 = bias[n + 1];
#pragma unroll
            for (int half = 0; half < 2; half++) {
                const int m = m0 + wm * 32 + mt * 16 + erow + half * 8;
                float v0 = acc[mt][nt][half * 2 + 0] + b0;
                float v1 = acc[mt][nt][half * 2 + 1] + b1;
                if (MODE == 0) {
                    v0 *= scale; v1 *= scale;
                    const int bb = m >> 10, s = m & 1023, hh = n >> 6, d = n & 63;
                    const size_t idx = ((size_t)(bb * Hc + hh) * Sc + s) * Dk + d;
                    __nv_bfloat16 h0 = __float2bfloat16_rn(v0);
                    __nv_bfloat16 h1 = __float2bfloat16_rn(v1);
                    __nv_bfloat16 l0 = __float2bfloat16_rn(v0 - __bfloat162float(h0));
                    __nv_bfloat16 l1 = __float2bfloat16_rn(v1 - __bfloat162float(h1));
                    ushort2 uh; uh.x = __bfloat16_as_ushort(h0); uh.y = __bfloat16_as_ushort(h1);
                    ushort2 ul; ul.x = __bfloat16_as_ushort(l0); ul.y = __bfloat16_as_ushort(l1);
                    *(ushort2*)&((unsigned short*)C0)[idx] = uh;
                    *(ushort2*)&((unsigned short*)C1)[idx] = ul;
                } else if (MODE == 2) {
                    const int bb = m >> 10, s = m & 1023, hh = n >> 6, d = n & 63;
                    const size_t idx = ((size_t)(bb * Hc + hh) * Dk + d) * Sc + s;
                    ((__half*)C0)[idx] = __float2half_rn(v0);
                    ((__half*)C0)[idx + Sc] = __float2half_rn(v1);
                } else {
                    const size_t idx = (size_t)m * 1024 + n;
                    float2 r = *(const float2*)&residual[idx];
                    float2 v; v.x = v0 + r.x; v.y = v1 + r.y;
                    *(float2*)&((float*)C0)[idx] = v;
                }
            }
        }
    }
}

// ===========================================================================
// scores kernel: S = Q.K^T (bf16 split, K=64), mask fused.
// R6 known-good: 256 threads, warp grid 4x2. grid (8 ntile, 8 mtile, 64 bh).
// ===========================================================================
#define SC_SMEM_SZ (4 * GT_TILEB)   // 73728

__global__ __launch_bounds__(256, 1)
void scores_kernel(const int* __restrict__ mask, float* __restrict__ S)
{
    extern __shared__ char smem[];
    const uint32_t sb = smem_to_u32(smem);
    const int tid = threadIdx.x;
    const int wid = tid >> 5, lane = tid & 31;
    const int wm = wid & 3, wn = wid >> 2;
    const int bh = blockIdx.z, b = bh >> 4;
    const int m0 = blockIdx.y * 128, n0 = blockIdx.x * 128;

    const size_t base = (size_t)bh * (Sc * Dk);
    const int crow = tid >> 1;
    const int chalf = tid & 1;
    const unsigned short* gsrc[4] = {
        g_Qh + base + (size_t)(m0 + crow) * 64 + chalf * 32,
        g_Ql + base + (size_t)(m0 + crow) * 64 + chalf * 32,
        g_Kh + base + (size_t)(n0 + crow) * 64 + chalf * 32,
        g_Kl + base + (size_t)(n0 + crow) * 64 + chalf * 32};
    const uint32_t srow = crow * (GT_ROW * 2) + chalf * 64;

#pragma unroll
    for (int tile = 0; tile < 4; tile++) {
        uint32_t s = sb + tile * GT_TILEB + srow;
#pragma unroll
        for (int i = 0; i < 4; i++)
            CP_ASYNC16(s + i * 16, gsrc[tile] + i * 8);
    }
    CP_COMMIT();

    float acc[2][8][4];
#pragma unroll
    for (int mt = 0; mt < 2; mt++)
#pragma unroll
        for (int nt = 0; nt < 8; nt++)
#pragma unroll
            for (int j = 0; j < 4; j++) acc[mt][nt][j] = 0.f;

    const int lg = lane >> 3, lr = lane & 7;
    const int rowoff = (lg & 1) * 8 + lr;
    const uint32_t kquad = (lg >> 1) * 16;

    CP_WAIT0();
    __syncthreads();

#pragma unroll
    for (int ks = 0; ks < 4; ks++) {
        const uint32_t kb = ks * 32 + kquad;
        uint32_t ah[2][4], al[2][4];
#pragma unroll
        for (int mt = 0; mt < 2; mt++) {
            uint32_t r = (wm * 32 + mt * 16 + rowoff) * (GT_ROW * 2) + kb;
            LDMATRIX_X4(ah[mt][0], ah[mt][1], ah[mt][2], ah[mt][3], sb + r);
            LDMATRIX_X4(al[mt][0], al[mt][1], al[mt][2], al[mt][3],
                        sb + GT_TILEB + r);
        }
        uint32_t bhf[8][2], blf[8][2];
#pragma unroll
        for (int p = 0; p < 4; p++) {
            uint32_t r = (wn * 64 + p * 16 + rowoff) * (GT_ROW * 2) + kb;
            LDMATRIX_X4(bhf[2 * p][0], bhf[2 * p + 1][0],
                        bhf[2 * p][1], bhf[2 * p + 1][1],
                        sb + 2 * GT_TILEB + r);
            LDMATRIX_X4(blf[2 * p][0], blf[2 * p + 1][0],
                        blf[2 * p][1], blf[2 * p + 1][1],
                        sb + 3 * GT_TILEB + r);
        }
#pragma unroll
        for (int mt = 0; mt < 2; mt++)
#pragma unroll
            for (int nt = 0; nt < 8; nt++) {
                MMA16816(acc[mt][nt], ah[mt], bhf[nt]);
                MMA16816(acc[mt][nt], ah[mt], blf[nt]);
                MMA16816(acc[mt][nt], al[mt], bhf[nt]);
            }
    }

    // epilogue: mask + store fp32 scores
    const int erow = lane >> 2;
    const int ecol = (lane & 3) * 2;
    float* Sb = S + (size_t)bh * Sc * Sc;
#pragma unroll
    for (int mt = 0; mt < 2; mt++) {
#pragma unroll
        for (int nt = 0; nt < 8; nt++) {
            const int n = n0 + wn * 64 + nt * 8 + ecol;
            const bool mk0 = (mask[b * Sc + n] == 0);
            const bool mk1 = (mask[b * Sc + n + 1] == 0);
#pragma unroll
            for (int half = 0; half < 2; half++) {
                const int m = m0 + wm * 32 + mt * 16 + erow + half * 8;
                float2 v;
                v.x = mk0 ? -1e9f : acc[mt][nt][half * 2 + 0];
                v.y = mk1 ? -1e9f : acc[mt][nt][half * 2 + 1];
                *(float2*)&Sb[(size_t)m * Sc + n] = v;
            }
        }
    }
}

// ===========================================================================
// FUSED softmax + ctx kernel.
// Block = 32 q-rows of one (b,h). 256 threads, 2 CTAs/SM.
// Phase 1: softmax on raw scores in gmem (in-place -> fp32 attn output),
//          fp16 probs parked in smem (row stride 2064B, ldmatrix-clean).
// Phase 2: ctx = P(smem) . V(gmem, cp.async double-buffered) via fp16 MMA,
//          32x64 output -> bf16 hi/lo split.
// grid (32 qtile, 64 bh).
// ===========================================================================
#define FX_PROWB 2064                          // 1024 halfs + 8 pad (16B shift/row)
#define FX_PBYTES (32 * FX_PROWB)              // 66048
#define FX_VROWB 144
#define FX_VTILEB (64 * FX_VROWB)              // 9216
#define FX_SMEM (FX_PBYTES + 2 * FX_VTILEB)    // 84480

__global__ __launch_bounds__(256, 2)
void softmax_ctx_kernel(float* __restrict__ S,
                        unsigned short* __restrict__ Chi,
                        unsigned short* __restrict__ Clo)
{
    extern __shared__ char smem[];
    const uint32_t sb = smem_to_u32(smem);
    const uint32_t sbV = sb + FX_PBYTES;
    const int tid = threadIdx.x;
    const int wid = tid >> 5, lane = tid & 31;
    const int bh = blockIdx.y, b = bh >> 4, h = bh & 15;
    const int m0 = blockIdx.x * 32;

    float* Sb = S + ((size_t)bh * Sc + m0) * Sc;
    const __half* Vb = g_VT + (size_t)bh * (Dk * Sc);

    // V tile loader: 64 rows(d) x 64 halfs(k), 2 threads/row on first 128 thr
    auto loadV = [&](int stg, int kt) {
        if (tid < 128) {
            const int brow = tid >> 1, bhalf = tid & 1;
            const __half* gbp = Vb + (size_t)brow * 1024 + kt * 64 + bhalf * 32;
            uint32_t sB = sbV + stg * FX_VTILEB + brow * FX_VROWB + bhalf * 64;
#pragma unroll
            for (int i = 0; i < 4; i++)
                CP_ASYNC16(sB + i * 16, gbp + i * 8);
        }
        CP_COMMIT();
    };

    // prefetch V tile 0 (independent of P)
    loadV(0, 0);

    // ---- phase 1: softmax, one warp handles 4 rows ----
#pragma unroll
    for (int r4 = 0; r4 < 4; r4++) {
        const int row = wid * 4 + r4;
        float* rp = Sb + (size_t)row * Sc;
        float4 v[8];
        float mx = -3.4e38f;
#pragma unroll
        for (int i = 0; i < 8; i++) {
            v[i] = *(const float4*)&rp[lane * 4 + i * 128];
            mx = fmaxf(mx, fmaxf(fmaxf(v[i].x, v[i].y), fmaxf(v[i].z, v[i].w)));
        }
#pragma unroll
        for (int o = 16; o; o >>= 1) mx = fmaxf(mx, __shfl_xor_sync(~0u, mx, o));
        float sum = 0.f;
#pragma unroll
        for (int i = 0; i < 8; i++) {
            v[i].x = expf(v[i].x - mx); v[i].y = expf(v[i].y - mx);
            v[i].z = expf(v[i].z - mx); v[i].w = expf(v[i].w - mx);
            sum += (v[i].x + v[i].y) + (v[i].z + v[i].w);
        }
#pragma unroll
        for (int o = 16; o; o >>= 1) sum += __shfl_xor_sync(~0u, sum, o);
        const float inv = 1.f / sum;
        const uint32_t srow = sb + row * FX_PROWB;
#pragma unroll
        for (int i = 0; i < 8; i++) {
            float4 p;
            p.x = v[i].x * inv; p.y = v[i].y * inv;
            p.z = v[i].z * inv; p.w = v[i].w * inv;
            *(float4*)&rp[lane * 4 + i * 128] = p;
            __half2 h0 = __floats2half2_rn(p.x, p.y);
            __half2 h1 = __floats2half2_rn(p.z, p.w);
            asm volatile("st.shared.v2.b32 [%0], {%1, %2};"
                :: "r"(srow + (lane * 4 + i * 128) * 2),
                   "r"(*(uint32_t*)&h0), "r"(*(uint32_t*)&h1) : "memory");
        }
    }
    __syncthreads();     // P smem complete

    // ---- phase 2: ctx = P . V ----
    const int wm = wid & 1, wn = wid >> 1;    // 2(m) x 4(n) warp grid
    float acc[2][4];
#pragma unroll
    for (int nt = 0; nt < 2; nt++)
#pragma unroll
        for (int j = 0; j < 4; j++) acc[nt][j] = 0.f;

    const int lg = lane >> 3, lr = lane & 7;
    const int rowoff = (lg & 1) * 8 + lr;
    const uint32_t kquad = (lg >> 1) * 16;

    CP_WAIT0();          // V tile 0 ready
    __syncthreads();

    for (int t = 0; t < 16; t++) {
        const int buf = t & 1;
        if (t + 1 < 16) loadV(buf ^ 1, t + 1);

        const uint32_t sV = sbV + buf * FX_VTILEB;
#pragma unroll
        for (int ks = 0; ks < 4; ks++) {
            const uint32_t kb = ks * 32 + kquad;
            uint32_t af[4];
            {
                uint32_t r = sb + (wm * 16 + rowoff) * FX_PROWB + t * 128 + kb;
                LDMATRIX_X4(af[0], af[1], af[2], af[3], r);
            }
            uint32_t bf[2][2];
            {
                uint32_t r = sV + (wn * 16 + rowoff) * FX_VROWB + kb;
                LDMATRIX_X4(bf[0][0], bf[1][0], bf[0][1], bf[1][1], r);
            }
            MMA16816F16(acc[0], af, bf[0]);
            MMA16816F16(acc[1], af, bf[1]);
        }
        if (t + 1 < 16) CP_WAIT0();
        __syncthreads();
    }

    // ---- epilogue: bf16 hi/lo split -> g_ch/g_cl ----
    const int erow = lane >> 2;
    const int ecol = (lane & 3) * 2;
#pragma unroll
    for (int nt = 0; nt < 2; nt++) {
        const int d = wn * 16 + nt * 8 + ecol;
#pragma unroll
        for (int half = 0; half < 2; half++) {
            const int q = m0 + wm * 16 + erow + half * 8;
            float v0 = acc[nt][half * 2 + 0];
            float v1 = acc[nt][half * 2 + 1];
            __nv_bfloat16 h0 = __float2bfloat16_rn(v0);
            __nv_bfloat16 h1 = __float2bfloat16_rn(v1);
            __nv_bfloat16 l0 = __float2bfloat16_rn(v0 - __bfloat162float(h0));
            __nv_bfloat16 l1 = __float2bfloat16_rn(v1 - __bfloat162float(h1));
            const size_t idx = ((size_t)(b * Sc) + q) * 1024 + h * Dk + d;
            ushort2 uh; uh.x = __bfloat16_as_ushort(h0); uh.y = __bfloat16_as_ushort(h1);
            ushort2 ul; ul.x = __bfloat16_as_ushort(l0); ul.y = __bfloat16_as_ushort(l1);
            *(ushort2*)&Chi[idx] = uh;
            *(ushort2*)&Clo[idx] = ul;
        }
    }
}

// ===========================================================================
// LayerNorm
// ===========================================================================
__global__ __launch_bounds__(256) void ln_kernel(
    const float* __restrict__ X, const float* __restrict__ gamma,
    const float* __restrict__ beta, float* __restrict__ out)
{
    __shared__ float red1[8];
    __shared__ float red2[8];
    const int row = blockIdx.x;
    const int tid = threadIdx.x;
    const float* x = X + (size_t)row * 1024;

    float v[4];
    float s = 0.f;
#pragma unroll
    for (int i = 0; i < 4; i++) { v[i] = x[tid + i * 256]; s += v[i]; }
#pragma unroll
    for (int o = 16; o; o >>= 1) s += __shfl_xor_sync(~0u, s, o);
    if ((tid & 31) == 0) red1[tid >> 5] = s;
    __syncthreads();
    if (tid < 32) {
        float t = (tid < 8) ? red1[tid] : 0.f;
#pragma unroll
        for (int o = 4; o; o >>= 1) t += __shfl_xor_sync(~0u, t, o);
        if (tid == 0) red1[0] = t;
    }
    __syncthreads();
    const float mu = red1[0] * (1.f / 1024.f);

    float ss = 0.f;
#pragma unroll
    for (int i = 0; i < 4; i++) { float d = v[i] - mu; ss += d * d; }
#pragma unroll
    for (int o = 16; o; o >>= 1) ss += __shfl_xor_sync(~0u, ss, o);
    if ((tid & 31) == 0) red2[tid >> 5] = ss;
    __syncthreads();
    if (tid < 32) {
        float t = (tid < 8) ? red2[tid] : 0.f;
#pragma unroll
        for (int o = 4; o; o >>= 1) t += __shfl_xor_sync(~0u, t, o);
        if (tid == 0) red2[0] = t;
    }
    __syncthreads();
    const float var = red2[0] * (1.f / 1024.f);
    const float rs = rsqrtf(var + 1e-5f);

#pragma unroll
    for (int i = 0; i < 4; i++) {
        const int c = tid + i * 256;
        out[(size_t)row * 1024 + c] = (v[i] - mu) * rs * gamma[c] + beta[c];
    }
}

// ===========================================================================
// Launch
// ===========================================================================
extern "C" void kernel_launch(void* const* d_in, const int* in_sizes, int n_in,
                              void* d_out, int out_size)
{
    const float* memory = (const float*)d_in[0];
    const float* dec    = (const float*)d_in[1];
    const int*   mask   = (const int*)d_in[2];
    const float* Wq = (const float*)d_in[3];
    const float* bq = (const float*)d_in[4];
    const float* Wk = (const float*)d_in[5];
    const float* bk = (const float*)d_in[6];
    const float* Wv = (const float*)d_in[7];
    const float* bv = (const float*)d_in[8];
    const float* Wo = (const float*)d_in[9];
    const float* bo = (const float*)d_in[10];
    const float* gamma = (const float*)d_in[11];
    const float* beta  = (const float*)d_in[12];

    float* out  = (float*)d_out;
    float* attn = out + (size_t)Bc * Sc * Dm;

    void *pX, *pmh, *pml, *pdh, *pdl, *pch, *pcl;
    cudaGetSymbolAddress(&pX, g_X);
    cudaGetSymbolAddress(&pmh, g_mh); cudaGetSymbolAddress(&pml, g_ml);
    cudaGetSymbolAddress(&pdh, g_dh); cudaGetSymbolAddress(&pdl, g_dl);
    cudaGetSymbolAddress(&pch, g_ch); cudaGetSymbolAddress(&pcl, g_cl);
    void *pqh, *pql, *pkh, *pkl, *pvh, *pvl, *poh, *pol;
    cudaGetSymbolAddress(&pqh, g_WqTh); cudaGetSymbolAddress(&pql, g_WqTl);
    cudaGetSymbolAddress(&pkh, g_WkTh); cudaGetSymbolAddress(&pkl, g_WkTl);
    cudaGetSymbolAddress(&pvh, g_WvTh); cudaGetSymbolAddress(&pvl, g_WvTl);
    cudaGetSymbolAddress(&poh, g_WoTh); cudaGetSymbolAddress(&pol, g_WoTl);
    void *pQh, *pQl, *pKh, *pKl, *pVT;
    cudaGetSymbolAddress(&pQh, g_Qh); cudaGetSymbolAddress(&pQl, g_Ql);
    cudaGetSymbolAddress(&pKh, g_Kh); cudaGetSymbolAddress(&pKl, g_Kl);
    cudaGetSymbolAddress(&pVT, g_VT);

    const int NACT4 = Bc * Sc * Dm / 4;

    // ---- prep (2 launches) ----
    SplitArgs sa;
    sa.src[0] = memory; sa.hi[0] = (unsigned short*)pmh; sa.lo[0] = (unsigned short*)pml;
    sa.src[1] = dec;    sa.hi[1] = (unsigned short*)pdh; sa.lo[1] = (unsigned short*)pdl;
    split2_kernel<<<dim3(NACT4 / 256, 2), 256>>>(sa, NACT4);

    TSArgs ta;
    ta.W[0] = Wq; ta.hi[0] = (unsigned short*)pqh; ta.lo[0] = (unsigned short*)pql;
    ta.W[1] = Wk; ta.hi[1] = (unsigned short*)pkh; ta.lo[1] = (unsigned short*)pkl;
    ta.W[2] = Wv; ta.hi[2] = (unsigned short*)pvh; ta.lo[2] = (unsigned short*)pvl;
    ta.W[3] = Wo; ta.hi[3] = (unsigned short*)poh; ta.lo[3] = (unsigned short*)pol;
    transsplit4_kernel<<<dim3(16, 16, 4), 256>>>(ta);

    // ---- projections (R6 known-good config) ----
    cudaFuncSetAttribute(gemm_mma<0>, cudaFuncAttributeMaxDynamicSharedMemorySize, GT_SMEM_SZ);
    cudaFuncSetAttribute(gemm_mma<1>, cudaFuncAttributeMaxDynamicSharedMemorySize, GT_SMEM_SZ);
    cudaFuncSetAttribute(gemm_mma<2>, cudaFuncAttributeMaxDynamicSharedMemorySize, GT_SMEM_SZ);
    const dim3 gg(8, 32), gt(256);
    gemm_mma<0><<<gg, gt, GT_SMEM_SZ>>>((unsigned short*)pmh, (unsigned short*)pml,
                                        (unsigned short*)pqh, (unsigned short*)pql,
                                        bq, nullptr, pQh, pQl, 0.125f);
    gemm_mma<0><<<gg, gt, GT_SMEM_SZ>>>((unsigned short*)pmh, (unsigned short*)pml,
                                        (unsigned short*)pkh, (unsigned short*)pkl,
                                        bk, nullptr, pKh, pKl, 1.0f);
    gemm_mma<2><<<gg, gt, GT_SMEM_SZ>>>((unsigned short*)pdh, (unsigned short*)pdl,
                                        (unsigned short*)pvh, (unsigned short*)pvl,
                                        bv, nullptr, pVT, nullptr, 1.0f);

    // ---- attention: scores -> fused softmax+ctx ----
    cudaFuncSetAttribute(scores_kernel, cudaFuncAttributeMaxDynamicSharedMemorySize, SC_SMEM_SZ);
    scores_kernel<<<dim3(8, 8, Bc * Hc), 256, SC_SMEM_SZ>>>(mask, attn);

    cudaFuncSetAttribute(softmax_ctx_kernel, cudaFuncAttributeMaxDynamicSharedMemorySize, FX_SMEM);
    softmax_ctx_kernel<<<dim3(32, Bc * Hc), 256, FX_SMEM>>>(attn,
                                                            (unsigned short*)pch,
                                                            (unsigned short*)pcl);

    // ---- output projection + residual, then LayerNorm ----
    gemm_mma<1><<<gg, gt, GT_SMEM_SZ>>>((unsigned short*)pch, (unsigned short*)pcl,
                                        (unsigned short*)poh, (unsigned short*)pol,
                                        bo, memory, pX, nullptr, 1.0f);
    ln_kernel<<<Bc * Sc, 256>>>((const float*)pX, gamma, beta, out);
}

// round 10
// speedup vs baseline: 1.0031x; 1.0031x over previous
#include <cuda_runtime.h>
#include <cuda_bf16.h>
#include <cuda_fp16.h>
#include <cstdint>
#include <math.h>

#define Bc 4
#define Sc 1024
#define Dm 1024
#define Hc 16
#define Dk 64

// -------- device scratch (allocation-free: static device globals) --------
__device__ float g_X[Bc * Sc * Dm];        // pre-LN activations

// bf16 split scratch
__device__ __align__(256) unsigned short g_mh[4194304], g_ml[4194304];   // memory hi/lo
__device__ __align__(256) unsigned short g_dh[4194304], g_dl[4194304];   // decoder hi/lo
__device__ __align__(256) unsigned short g_ch[4194304], g_cl[4194304];   // ctx hi/lo
__device__ __align__(256) unsigned short g_WqTh[1048576], g_WqTl[1048576];
__device__ __align__(256) unsigned short g_WkTh[1048576], g_WkTl[1048576];
__device__ __align__(256) unsigned short g_WvTh[1048576], g_WvTl[1048576];
__device__ __align__(256) unsigned short g_WoTh[1048576], g_WoTl[1048576];
// attention operands
__device__ __align__(256) unsigned short g_Qh[4194304], g_Ql[4194304];   // [b,h,s,d] bf16
__device__ __align__(256) unsigned short g_Kh[4194304], g_Kl[4194304];   // [b,h,s,d] bf16
__device__ __align__(256) __half g_VT[4194304];                          // [b,h,d,s] fp16

// ======================== PTX helpers (base sm_80+ ISA only) ==============
__device__ __forceinline__ uint32_t smem_to_u32(const void* p) {
    uint32_t a;
    asm("{ .reg .u64 t; cvta.to.shared.u64 t, %1; cvt.u32.u64 %0, t; }"
        : "=r"(a) : "l"(p));
    return a;
}

#define CP_ASYNC16(sm, gp) \
    asm volatile("cp.async.cg.shared.global [%0], [%1], 16;" \
        :: "r"(sm), "l"(gp) : "memory")
#define CP_COMMIT() asm volatile("cp.async.commit_group;" ::: "memory")
#define CP_WAIT0()  asm volatile("cp.async.wait_group 0;" ::: "memory")

#define LDMATRIX_X4(r0, r1, r2, r3, addr) \
    asm volatile("ldmatrix.sync.aligned.m8n8.x4.shared.b16 {%0,%1,%2,%3}, [%4];" \
        : "=r"(r0), "=r"(r1), "=r"(r2), "=r"(r3) : "r"(addr))

#define MMA16816(C, A, B) \
    asm volatile("mma.sync.aligned.m16n8k16.row.col.f32.bf16.bf16.f32 " \
        "{%0,%1,%2,%3}, {%4,%5,%6,%7}, {%8,%9}, {%0,%1,%2,%3};" \
        : "+f"((C)[0]), "+f"((C)[1]), "+f"((C)[2]), "+f"((C)[3]) \
        : "r"((A)[0]), "r"((A)[1]), "r"((A)[2]), "r"((A)[3]), \
          "r"((B)[0]), "r"((B)[1]))

#define MMA16816F16(C, A, B) \
    asm volatile("mma.sync.aligned.m16n8k16.row.col.f32.f16.f16.f32 " \
        "{%0,%1,%2,%3}, {%4,%5,%6,%7}, {%8,%9}, {%0,%1,%2,%3};" \
        : "+f"((C)[0]), "+f"((C)[1]), "+f"((C)[2]), "+f"((C)[3]) \
        : "r"((A)[0]), "r"((A)[1]), "r"((A)[2]), "r"((A)[3]), \
          "r"((B)[0]), "r"((B)[1]))

// ===========================================================================
// split2: fp32 -> bf16 hi + lo, two sources batched via blockIdx.y
// ===========================================================================
struct SplitArgs {
    const float* src[2];
    unsigned short* hi[2];
    unsigned short* lo[2];
};
__global__ __launch_bounds__(256) void split2_kernel(SplitArgs a, int n4)
{
    const int w = blockIdx.y;
    int i = blockIdx.x * 256 + threadIdx.x;
    if (i >= n4) return;
    float4 v = ((const float4*)a.src[w])[i];
    float f[4] = {v.x, v.y, v.z, v.w};
#pragma unroll
    for (int j = 0; j < 4; j++) {
        __nv_bfloat16 h = __float2bfloat16_rn(f[j]);
        __nv_bfloat16 l = __float2bfloat16_rn(f[j] - __bfloat162float(h));
        a.hi[w][i * 4 + j] = __bfloat16_as_ushort(h);
        a.lo[w][i * 4 + j] = __bfloat16_as_ushort(l);
    }
}

// ===========================================================================
// transsplit4: W[k][n] fp32 -> WT_hi[n][k], WT_lo[n][k] bf16, 4 weights (z)
// ===========================================================================
struct TSArgs {
    const float* W[4];
    unsigned short* hi[4];
    unsigned short* lo[4];
};
__global__ __launch_bounds__(256) void transsplit4_kernel(TSArgs a)
{
    __shared__ unsigned short sh[64][68];
    __shared__ unsigned short sl[64][68];
    const int w = blockIdx.z;
    const float* W = a.W[w];
    const int k0 = blockIdx.y << 6, n0 = blockIdx.x << 6;
    const int r = threadIdx.x >> 4, c = (threadIdx.x & 15) << 2;
#pragma unroll
    for (int it = 0; it < 4; it++) {
        int row = r + it * 16;
        float4 v = *(const float4*)&W[(size_t)(k0 + row) * 1024 + n0 + c];
        float f[4] = {v.x, v.y, v.z, v.w};
#pragma unroll
        for (int j = 0; j < 4; j++) {
            __nv_bfloat16 h = __float2bfloat16_rn(f[j]);
            __nv_bfloat16 l = __float2bfloat16_rn(f[j] - __bfloat162float(h));
            sh[row][c + j] = __bfloat16_as_ushort(h);
            sl[row][c + j] = __bfloat16_as_ushort(l);
        }
    }
    __syncthreads();
#pragma unroll
    for (int it = 0; it < 4; it++) {
        int nn = r + it * 16;
#pragma unroll
        for (int j = 0; j < 4; j++) {
            a.hi[w][(size_t)(n0 + nn) * 1024 + k0 + c + j] = sh[c + j][nn];
            a.lo[w][(size_t)(n0 + nn) * 1024 + k0 + c + j] = sl[c + j][nn];
        }
    }
}

// ===========================================================================
// HMMA GEMM (bf16 3-product split), 128x128 tile, BK=64, double-buffered.
// R6 known-good: 256 threads, warp grid 4(M) x 2(N), warp tile 32x64.
// MODE 0: Q/K proj -> bf16 hi/lo scatter [b,h,s,d], (acc+bias)*scale
// MODE 1: out proj -> fp32 row-major, acc + bias + residual
// MODE 2: V proj -> fp16 transposed [b,h,d,s], acc + bias
// ===========================================================================
#define GT_ROW   72
#define GT_TILEB (128 * GT_ROW * 2)    // 18432
#define GT_STAGEB (4 * GT_TILEB)       // 73728
#define GT_SMEM_SZ (2 * GT_STAGEB)     // 147456

template <int MODE>
__global__ __launch_bounds__(256, 1)
void gemm_mma(const unsigned short* __restrict__ Ah, const unsigned short* __restrict__ Al,
              const unsigned short* __restrict__ Bh, const unsigned short* __restrict__ Bl,
              const float* __restrict__ bias, const float* __restrict__ residual,
              void* __restrict__ C0, void* __restrict__ C1, float scale)
{
    extern __shared__ char smem[];
    const uint32_t sb = smem_to_u32(smem);
    const int tid = threadIdx.x;
    const int wid = tid >> 5, lane = tid & 31;
    const int wm = wid & 3, wn = wid >> 2;
    const int m0 = blockIdx.y * 128, n0 = blockIdx.x * 128;

    const int crow = tid >> 1;
    const int cseg = (tid & 1) * 4;
    const unsigned short* gsrc[4] = {
        Ah + (size_t)(m0 + crow) * 1024, Al + (size_t)(m0 + crow) * 1024,
        Bh + (size_t)(n0 + crow) * 1024, Bl + (size_t)(n0 + crow) * 1024};
    const uint32_t srow = crow * (GT_ROW * 2) + cseg * 16;

    auto load_stage = [&](int stg, int k0) {
#pragma unroll
        for (int tile = 0; tile < 4; tile++) {
            const unsigned short* g = gsrc[tile] + k0 + cseg * 8;
            uint32_t s = sb + stg * GT_STAGEB + tile * GT_TILEB + srow;
#pragma unroll
            for (int i = 0; i < 4; i++)
                CP_ASYNC16(s + i * 16, g + i * 8);
        }
        CP_COMMIT();
    };

    float acc[2][8][4];
#pragma unroll
    for (int mt = 0; mt < 2; mt++)
#pragma unroll
        for (int nt = 0; nt < 8; nt++)
#pragma unroll
            for (int j = 0; j < 4; j++) acc[mt][nt][j] = 0.f;

    const int lg = lane >> 3, lr = lane & 7;
    const int rowoff = (lg & 1) * 8 + lr;
    const uint32_t kquad = (lg >> 1) * 16;

    load_stage(0, 0);
    CP_WAIT0();
    __syncthreads();

    for (int t = 0; t < 16; t++) {
        const int buf = t & 1;
        if (t + 1 < 16) load_stage(buf ^ 1, (t + 1) * 64);

        const uint32_t stg = sb + buf * GT_STAGEB;
#pragma unroll
        for (int ks = 0; ks < 4; ks++) {
            const uint32_t kb = ks * 32 + kquad;
            uint32_t ah[2][4], al[2][4];
#pragma unroll
            for (int mt = 0; mt < 2; mt++) {
                uint32_t r = (wm * 32 + mt * 16 + rowoff) * (GT_ROW * 2) + kb;
                LDMATRIX_X4(ah[mt][0], ah[mt][1], ah[mt][2], ah[mt][3], stg + r);
                LDMATRIX_X4(al[mt][0], al[mt][1], al[mt][2], al[mt][3],
                            stg + GT_TILEB + r);
            }
            uint32_t bh[8][2], bl[8][2];
#pragma unroll
            for (int p = 0; p < 4; p++) {
                uint32_t r = (wn * 64 + p * 16 + rowoff) * (GT_ROW * 2) + kb;
                LDMATRIX_X4(bh[2 * p][0], bh[2 * p + 1][0],
                            bh[2 * p][1], bh[2 * p + 1][1],
                            stg + 2 * GT_TILEB + r);
                LDMATRIX_X4(bl[2 * p][0], bl[2 * p + 1][0],
                            bl[2 * p][1], bl[2 * p + 1][1],
                            stg + 3 * GT_TILEB + r);
            }
#pragma unroll
            for (int mt = 0; mt < 2; mt++)
#pragma unroll
                for (int nt = 0; nt < 8; nt++) {
                    MMA16816(acc[mt][nt], ah[mt], bh[nt]);
                    MMA16816(acc[mt][nt], ah[mt], bl[nt]);
                    MMA16816(acc[mt][nt], al[mt], bh[nt]);
                }
        }
        if (t + 1 < 16) CP_WAIT0();
        __syncthreads();
    }

    // ---- epilogue ----
    const int erow = lane >> 2;
    const int ecol = (lane & 3) * 2;
#pragma unroll
    for (int mt = 0; mt < 2; mt++) {
#pragma unroll
        for (int nt = 0; nt < 8; nt++) {
            const int n = n0 + wn * 64 + nt * 8 + ecol;
            const float b0 = bias[n], b1 = bias[n + 1];
#pragma unroll
            for (int half = 0; half < 2; half++) {
                const int m = m0 + wm * 32 + mt * 16 + erow + half * 8;
                float v0 = acc[mt][nt][half * 2 + 0] + b0;
                float v1 = acc[mt][nt][half * 2 + 1] + b1;
                if (MODE == 0) {
                    v0 *= scale; v1 *= scale;
                    const int bb = m >> 10, s = m & 1023, hh = n >> 6, d = n & 63;
                    const size_t idx = ((size_t)(bb * Hc + hh) * Sc + s) * Dk + d;
                    __nv_bfloat16 h0 = __float2bfloat16_rn(v0);
                    __nv_bfloat16 h1 = __float2bfloat16_rn(v1);
                    __nv_bfloat16 l0 = __float2bfloat16_rn(v0 - __bfloat162float(h0));
                    __nv_bfloat16 l1 = __float2bfloat16_rn(v1 - __bfloat162float(h1));
                    ushort2 uh; uh.x = __bfloat16_as_ushort(h0); uh.y = __bfloat16_as_ushort(h1);
                    ushort2 ul; ul.x = __bfloat16_as_ushort(l0); ul.y = __bfloat16_as_ushort(l1);
                    *(ushort2*)&((unsigned short*)C0)[idx] = uh;
                    *(ushort2*)&((unsigned short*)C1)[idx] = ul;
                } else if (MODE == 2) {
                    const int bb = m >> 10, s = m & 1023, hh = n >> 6, d = n & 63;
                    const size_t idx = ((size_t)(bb * Hc + hh) * Dk + d) * Sc + s;
                    ((__half*)C0)[idx] = __float2half_rn(v0);
                    ((__half*)C0)[idx + Sc] = __float2half_rn(v1);
                } else {
                    const size_t idx = (size_t)m * 1024 + n;
                    float2 r = *(const float2*)&residual[idx];
                    float2 v; v.x = v0 + r.x; v.y = v1 + r.y;
                    *(float2*)&((float*)C0)[idx] = v;
                }
            }
        }
    }
}

// ===========================================================================
// scores kernel: S = Q.K^T (bf16 split, K=64), mask fused.
// R6 known-good: 256 threads, warp grid 4x2. grid (8 ntile, 8 mtile, 64 bh).
// ===========================================================================
#define SC_SMEM_SZ (4 * GT_TILEB)   // 73728

__global__ __launch_bounds__(256, 1)
void scores_kernel(const int* __restrict__ mask, float* __restrict__ S)
{
    extern __shared__ char smem[];
    const uint32_t sb = smem_to_u32(smem);
    const int tid = threadIdx.x;
    const int wid = tid >> 5, lane = tid & 31;
    const int wm = wid & 3, wn = wid >> 2;
    const int bh = blockIdx.z, b = bh >> 4;
    const int m0 = blockIdx.y * 128, n0 = blockIdx.x * 128;

    const size_t base = (size_t)bh * (Sc * Dk);
    const int crow = tid >> 1;
    const int chalf = tid & 1;
    const unsigned short* gsrc[4] = {
        g_Qh + base + (size_t)(m0 + crow) * 64 + chalf * 32,
        g_Ql + base + (size_t)(m0 + crow) * 64 + chalf * 32,
        g_Kh + base + (size_t)(n0 + crow) * 64 + chalf * 32,
        g_Kl + base + (size_t)(n0 + crow) * 64 + chalf * 32};
    const uint32_t srow = crow * (GT_ROW * 2) + chalf * 64;

#pragma unroll
    for (int tile = 0; tile < 4; tile++) {
        uint32_t s = sb + tile * GT_TILEB + srow;
#pragma unroll
        for (int i = 0; i < 4; i++)
            CP_ASYNC16(s + i * 16, gsrc[tile] + i * 8);
    }
    CP_COMMIT();

    float acc[2][8][4];
#pragma unroll
    for (int mt = 0; mt < 2; mt++)
#pragma unroll
        for (int nt = 0; nt < 8; nt++)
#pragma unroll
            for (int j = 0; j < 4; j++) acc[mt][nt][j] = 0.f;

    const int lg = lane >> 3, lr = lane & 7;
    const int rowoff = (lg & 1) * 8 + lr;
    const uint32_t kquad = (lg >> 1) * 16;

    CP_WAIT0();
    __syncthreads();

#pragma unroll
    for (int ks = 0; ks < 4; ks++) {
        const uint32_t kb = ks * 32 + kquad;
        uint32_t ah[2][4], al[2][4];
#pragma unroll
        for (int mt = 0; mt < 2; mt++) {
            uint32_t r = (wm * 32 + mt * 16 + rowoff) * (GT_ROW * 2) + kb;
            LDMATRIX_X4(ah[mt][0], ah[mt][1], ah[mt][2], ah[mt][3], sb + r);
            LDMATRIX_X4(al[mt][0], al[mt][1], al[mt][2], al[mt][3],
                        sb + GT_TILEB + r);
        }
        uint32_t bhf[8][2], blf[8][2];
#pragma unroll
        for (int p = 0; p < 4; p++) {
            uint32_t r = (wn * 64 + p * 16 + rowoff) * (GT_ROW * 2) + kb;
            LDMATRIX_X4(bhf[2 * p][0], bhf[2 * p + 1][0],
                        bhf[2 * p][1], bhf[2 * p + 1][1],
                        sb + 2 * GT_TILEB + r);
            LDMATRIX_X4(blf[2 * p][0], blf[2 * p + 1][0],
                        blf[2 * p][1], blf[2 * p + 1][1],
                        sb + 3 * GT_TILEB + r);
        }
#pragma unroll
        for (int mt = 0; mt < 2; mt++)
#pragma unroll
            for (int nt = 0; nt < 8; nt++) {
                MMA16816(acc[mt][nt], ah[mt], bhf[nt]);
                MMA16816(acc[mt][nt], ah[mt], blf[nt]);
                MMA16816(acc[mt][nt], al[mt], bhf[nt]);
            }
    }

    // epilogue: mask + store fp32 scores
    const int erow = lane >> 2;
    const int ecol = (lane & 3) * 2;
    float* Sb = S + (size_t)bh * Sc * Sc;
#pragma unroll
    for (int mt = 0; mt < 2; mt++) {
#pragma unroll
        for (int nt = 0; nt < 8; nt++) {
            const int n = n0 + wn * 64 + nt * 8 + ecol;
            const bool mk0 = (mask[b * Sc + n] == 0);
            const bool mk1 = (mask[b * Sc + n + 1] == 0);
#pragma unroll
            for (int half = 0; half < 2; half++) {
                const int m = m0 + wm * 32 + mt * 16 + erow + half * 8;
                float2 v;
                v.x = mk0 ? -1e9f : acc[mt][nt][half * 2 + 0];
                v.y = mk1 ? -1e9f : acc[mt][nt][half * 2 + 1];
                *(float2*)&Sb[(size_t)m * Sc + n] = v;
            }
        }
    }
}

// ===========================================================================
// FUSED softmax + ctx kernel.
// Block = 32 q-rows of one (b,h). 256 threads, 2 CTAs/SM.
// Phase 1: softmax on raw scores in gmem (in-place -> fp32 attn output),
//          fp16 probs parked in smem (row stride 2064B, ldmatrix-clean).
// Phase 2: ctx = P(smem) . V(gmem, cp.async double-buffered) via fp16 MMA,
//          32x64 output -> bf16 hi/lo split.
// grid (32 qtile, 64 bh).
// ===========================================================================
#define FX_PROWB 2064                          // 1024 halfs + 8 pad (16B shift/row)
#define FX_PBYTES (32 * FX_PROWB)              // 66048
#define FX_VROWB 144
#define FX_VTILEB (64 * FX_VROWB)              // 9216
#define FX_SMEM (FX_PBYTES + 2 * FX_VTILEB)    // 84480

__global__ __launch_bounds__(256, 2)
void softmax_ctx_kernel(float* __restrict__ S,
                        unsigned short* __restrict__ Chi,
                        unsigned short* __restrict__ Clo)
{
    extern __shared__ char smem[];
    const uint32_t sb = smem_to_u32(smem);
    const uint32_t sbV = sb + FX_PBYTES;
    const int tid = threadIdx.x;
    const int wid = tid >> 5, lane = tid & 31;
    const int bh = blockIdx.y, b = bh >> 4, h = bh & 15;
    const int m0 = blockIdx.x * 32;

    float* Sb = S + ((size_t)bh * Sc + m0) * Sc;
    const __half* Vb = g_VT + (size_t)bh * (Dk * Sc);

    // V tile loader: 64 rows(d) x 64 halfs(k), 2 threads/row on first 128 thr
    auto loadV = [&](int stg, int kt) {
        if (tid < 128) {
            const int brow = tid >> 1, bhalf = tid & 1;
            const __half* gbp = Vb + (size_t)brow * 1024 + kt * 64 + bhalf * 32;
            uint32_t sB = sbV + stg * FX_VTILEB + brow * FX_VROWB + bhalf * 64;
#pragma unroll
            for (int i = 0; i < 4; i++)
                CP_ASYNC16(sB + i * 16, gbp + i * 8);
        }
        CP_COMMIT();
    };

    // prefetch V tile 0 (independent of P)
    loadV(0, 0);

    // ---- phase 1: softmax, one warp handles 4 rows ----
#pragma unroll
    for (int r4 = 0; r4 < 4; r4++) {
        const int row = wid * 4 + r4;
        float* rp = Sb + (size_t)row * Sc;
        float4 v[8];
        float mx = -3.4e38f;
#pragma unroll
        for (int i = 0; i < 8; i++) {
            v[i] = *(const float4*)&rp[lane * 4 + i * 128];
            mx = fmaxf(mx, fmaxf(fmaxf(v[i].x, v[i].y), fmaxf(v[i].z, v[i].w)));
        }
#pragma unroll
        for (int o = 16; o; o >>= 1) mx = fmaxf(mx, __shfl_xor_sync(~0u, mx, o));
        float sum = 0.f;
#pragma unroll
        for (int i = 0; i < 8; i++) {
            v[i].x = expf(v[i].x - mx); v[i].y = expf(v[i].y - mx);
            v[i].z = expf(v[i].z - mx); v[i].w = expf(v[i].w - mx);
            sum += (v[i].x + v[i].y) + (v[i].z + v[i].w);
        }
#pragma unroll
        for (int o = 16; o; o >>= 1) sum += __shfl_xor_sync(~0u, sum, o);
        const float inv = 1.f / sum;
        const uint32_t srow = sb + row * FX_PROWB;
#pragma unroll
        for (int i = 0; i < 8; i++) {
            float4 p;
            p.x = v[i].x * inv; p.y = v[i].y * inv;
            p.z = v[i].z * inv; p.w = v[i].w * inv;
            *(float4*)&rp[lane * 4 + i * 128] = p;
            __half2 h0 = __floats2half2_rn(p.x, p.y);
            __half2 h1 = __floats2half2_rn(p.z, p.w);
            asm volatile("st.shared.v2.b32 [%0], {%1, %2};"
                :: "r"(srow + (lane * 4 + i * 128) * 2),
                   "r"(*(uint32_t*)&h0), "r"(*(uint32_t*)&h1) : "memory");
        }
    }
    __syncthreads();     // P smem complete

    // ---- phase 2: ctx = P . V ----
    const int wm = wid & 1, wn = wid >> 1;    // 2(m) x 4(n) warp grid
    float acc[2][4];
#pragma unroll
    for (int nt = 0; nt < 2; nt++)
#pragma unroll
        for (int j = 0; j < 4; j++) acc[nt][j] = 0.f;

    const int lg = lane >> 3, lr = lane & 7;
    const int rowoff = (lg & 1) * 8 + lr;
    const uint32_t kquad = (lg >> 1) * 16;

    CP_WAIT0();          // V tile 0 ready
    __syncthreads();

    for (int t = 0; t < 16; t++) {
        const int buf = t & 1;
        if (t + 1 < 16) loadV(buf ^ 1, t + 1);

        const uint32_t sV = sbV + buf * FX_VTILEB;
#pragma unroll
        for (int ks = 0; ks < 4; ks++) {
            const uint32_t kb = ks * 32 + kquad;
            uint32_t af[4];
            {
                uint32_t r = sb + (wm * 16 + rowoff) * FX_PROWB + t * 128 + kb;
                LDMATRIX_X4(af[0], af[1], af[2], af[3], r);
            }
            uint32_t bf[2][2];
            {
                uint32_t r = sV + (wn * 16 + rowoff) * FX_VROWB + kb;
                LDMATRIX_X4(bf[0][0], bf[1][0], bf[0][1], bf[1][1], r);
            }
            MMA16816F16(acc[0], af, bf[0]);
            MMA16816F16(acc[1], af, bf[1]);
        }
        if (t + 1 < 16) CP_WAIT0();
        __syncthreads();
    }

    // ---- epilogue: bf16 hi/lo split -> g_ch/g_cl ----
    const int erow = lane >> 2;
    const int ecol = (lane & 3) * 2;
#pragma unroll
    for (int nt = 0; nt < 2; nt++) {
        const int d = wn * 16 + nt * 8 + ecol;
#pragma unroll
        for (int half = 0; half < 2; half++) {
            const int q = m0 + wm * 16 + erow + half * 8;
            float v0 = acc[nt][half * 2 + 0];
            float v1 = acc[nt][half * 2 + 1];
            __nv_bfloat16 h0 = __float2bfloat16_rn(v0);
            __nv_bfloat16 h1 = __float2bfloat16_rn(v1);
            __nv_bfloat16 l0 = __float2bfloat16_rn(v0 - __bfloat162float(h0));
            __nv_bfloat16 l1 = __float2bfloat16_rn(v1 - __bfloat162float(h1));
            const size_t idx = ((size_t)(b * Sc) + q) * 1024 + h * Dk + d;
            ushort2 uh; uh.x = __bfloat16_as_ushort(h0); uh.y = __bfloat16_as_ushort(h1);
            ushort2 ul; ul.x = __bfloat16_as_ushort(l0); ul.y = __bfloat16_as_ushort(l1);
            *(ushort2*)&Chi[idx] = uh;
            *(ushort2*)&Clo[idx] = ul;
        }
    }
}

// ===========================================================================
// LayerNorm
// ===========================================================================
__global__ __launch_bounds__(256) void ln_kernel(
    const float* __restrict__ X, const float* __restrict__ gamma,
    const float* __restrict__ beta, float* __restrict__ out)
{
    __shared__ float red1[8];
    __shared__ float red2[8];
    const int row = blockIdx.x;
    const int tid = threadIdx.x;
    const float* x = X + (size_t)row * 1024;

    float v[4];
    float s = 0.f;
#pragma unroll
    for (int i = 0; i < 4; i++) { v[i] = x[tid + i * 256]; s += v[i]; }
#pragma unroll
    for (int o = 16; o; o >>= 1) s += __shfl_xor_sync(~0u, s, o);
    if ((tid & 31) == 0) red1[tid >> 5] = s;
    __syncthreads();
    if (tid < 32) {
        float t = (tid < 8) ? red1[tid] : 0.f;
#pragma unroll
        for (int o = 4; o; o >>= 1) t += __shfl_xor_sync(~0u, t, o);
        if (tid == 0) red1[0] = t;
    }
    __syncthreads();
    const float mu = red1[0] * (1.f / 1024.f);

    float ss = 0.f;
#pragma unroll
    for (int i = 0; i < 4; i++) { float d = v[i] - mu; ss += d * d; }
#pragma unroll
    for (int o = 16; o; o >>= 1) ss += __shfl_xor_sync(~0u, ss, o);
    if ((tid & 31) == 0) red2[tid >> 5] = ss;
    __syncthreads();
    if (tid < 32) {
        float t = (tid < 8) ? red2[tid] : 0.f;
#pragma unroll
        for (int o = 4; o; o >>= 1) t += __shfl_xor_sync(~0u, t, o);
        if (tid == 0) red2[0] = t;
    }
    __syncthreads();
    const float var = red2[0] * (1.f / 1024.f);
    const float rs = rsqrtf(var + 1e-5f);

#pragma unroll
    for (int i = 0; i < 4; i++) {
        const int c = tid + i * 256;
        out[(size_t)row * 1024 + c] = (v[i] - mu) * rs * gamma[c] + beta[c];
    }
}

// ===========================================================================
// Launch
// ===========================================================================
extern "C" void kernel_launch(void* const* d_in, const int* in_sizes, int n_in,
                              void* d_out, int out_size)
{
    const float* memory = (const float*)d_in[0];
    const float* dec    = (const float*)d_in[1];
    const int*   mask   = (const int*)d_in[2];
    const float* Wq = (const float*)d_in[3];
    const float* bq = (const float*)d_in[4];
    const float* Wk = (const float*)d_in[5];
    const float* bk = (const float*)d_in[6];
    const float* Wv = (const float*)d_in[7];
    const float* bv = (const float*)d_in[8];
    const float* Wo = (const float*)d_in[9];
    const float* bo = (const float*)d_in[10];
    const float* gamma = (const float*)d_in[11];
    const float* beta  = (const float*)d_in[12];

    float* out  = (float*)d_out;
    float* attn = out + (size_t)Bc * Sc * Dm;

    void *pX, *pmh, *pml, *pdh, *pdl, *pch, *pcl;
    cudaGetSymbolAddress(&pX, g_X);
    cudaGetSymbolAddress(&pmh, g_mh); cudaGetSymbolAddress(&pml, g_ml);
    cudaGetSymbolAddress(&pdh, g_dh); cudaGetSymbolAddress(&pdl, g_dl);
    cudaGetSymbolAddress(&pch, g_ch); cudaGetSymbolAddress(&pcl, g_cl);
    void *pqh, *pql, *pkh, *pkl, *pvh, *pvl, *poh, *pol;
    cudaGetSymbolAddress(&pqh, g_WqTh); cudaGetSymbolAddress(&pql, g_WqTl);
    cudaGetSymbolAddress(&pkh, g_WkTh); cudaGetSymbolAddress(&pkl, g_WkTl);
    cudaGetSymbolAddress(&pvh, g_WvTh); cudaGetSymbolAddress(&pvl, g_WvTl);
    cudaGetSymbolAddress(&poh, g_WoTh); cudaGetSymbolAddress(&pol, g_WoTl);
    void *pQh, *pQl, *pKh, *pKl, *pVT;
    cudaGetSymbolAddress(&pQh, g_Qh); cudaGetSymbolAddress(&pQl, g_Ql);
    cudaGetSymbolAddress(&pKh, g_Kh); cudaGetSymbolAddress(&pKl, g_Kl);
    cudaGetSymbolAddress(&pVT, g_VT);

    const int NACT4 = Bc * Sc * Dm / 4;

    // ---- prep (2 launches) ----
    SplitArgs sa;
    sa.src[0] = memory; sa.hi[0] = (unsigned short*)pmh; sa.lo[0] = (unsigned short*)pml;
    sa.src[1] = dec;    sa.hi[1] = (unsigned short*)pdh; sa.lo[1] = (unsigned short*)pdl;
    split2_kernel<<<dim3(NACT4 / 256, 2), 256>>>(sa, NACT4);

    TSArgs ta;
    ta.W[0] = Wq; ta.hi[0] = (unsigned short*)pqh; ta.lo[0] = (unsigned short*)pql;
    ta.W[1] = Wk; ta.hi[1] = (unsigned short*)pkh; ta.lo[1] = (unsigned short*)pkl;
    ta.W[2] = Wv; ta.hi[2] = (unsigned short*)pvh; ta.lo[2] = (unsigned short*)pvl;
    ta.W[3] = Wo; ta.hi[3] = (unsigned short*)poh; ta.lo[3] = (unsigned short*)pol;
    transsplit4_kernel<<<dim3(16, 16, 4), 256>>>(ta);

    // ---- projections (R6 known-good config) ----
    cudaFuncSetAttribute(gemm_mma<0>, cudaFuncAttributeMaxDynamicSharedMemorySize, GT_SMEM_SZ);
    cudaFuncSetAttribute(gemm_mma<1>, cudaFuncAttributeMaxDynamicSharedMemorySize, GT_SMEM_SZ);
    cudaFuncSetAttribute(gemm_mma<2>, cudaFuncAttributeMaxDynamicSharedMemorySize, GT_SMEM_SZ);
    const dim3 gg(8, 32), gt(256);
    gemm_mma<0><<<gg, gt, GT_SMEM_SZ>>>((unsigned short*)pmh, (unsigned short*)pml,
                                        (unsigned short*)pqh, (unsigned short*)pql,
                                        bq, nullptr, pQh, pQl, 0.125f);
    gemm_mma<0><<<gg, gt, GT_SMEM_SZ>>>((unsigned short*)pmh, (unsigned short*)pml,
                                        (unsigned short*)pkh, (unsigned short*)pkl,
                                        bk, nullptr, pKh, pKl, 1.0f);
    gemm_mma<2><<<gg, gt, GT_SMEM_SZ>>>((unsigned short*)pdh, (unsigned short*)pdl,
                                        (unsigned short*)pvh, (unsigned short*)pvl,
                                        bv, nullptr, pVT, nullptr, 1.0f);

    // ---- attention: scores -> fused softmax+ctx ----
    cudaFuncSetAttribute(scores_kernel, cudaFuncAttributeMaxDynamicSharedMemorySize, SC_SMEM_SZ);
    scores_kernel<<<dim3(8, 8, Bc * Hc), 256, SC_SMEM_SZ>>>(mask, attn);

    cudaFuncSetAttribute(softmax_ctx_kernel, cudaFuncAttributeMaxDynamicSharedMemorySize, FX_SMEM);
    softmax_ctx_kernel<<<dim3(32, Bc * Hc), 256, FX_SMEM>>>(attn,
                                                            (unsigned short*)pch,
                                                            (unsigned short*)pcl);

    // ---- output projection + residual, then LayerNorm ----
    gemm_mma<1><<<gg, gt, GT_SMEM_SZ>>>((unsigned short*)pch, (unsigned short*)pcl,
                                        (unsigned short*)poh, (unsigned short*)pol,
                                        bo, memory, pX, nullptr, 1.0f);
    ln_kernel<<<Bc * Sc, 256>>>((const float*)pX, gamma, beta, out);
}

// round 11
// speedup vs baseline: 1.0040x; 1.0009x over previous
#include <cuda_runtime.h>
#include <cuda_bf16.h>
#include <cuda_fp16.h>
#include <cstdint>
#include <math.h>

#define Bc 4
#define Sc 1024
#define Dm 1024
#define Hc 16
#define Dk 64

// -------- device scratch (allocation-free: static device globals) --------
__device__ float g_X[Bc * Sc * Dm];        // pre-LN activations

// bf16 split scratch
__device__ __align__(256) unsigned short g_mh[4194304], g_ml[4194304];   // memory hi/lo
__device__ __align__(256) unsigned short g_dh[4194304], g_dl[4194304];   // decoder hi/lo
__device__ __align__(256) unsigned short g_ch[4194304], g_cl[4194304];   // ctx hi/lo
__device__ __align__(256) unsigned short g_WqTh[1048576], g_WqTl[1048576];
__device__ __align__(256) unsigned short g_WkTh[1048576], g_WkTl[1048576];
__device__ __align__(256) unsigned short g_WvTh[1048576], g_WvTl[1048576];
__device__ __align__(256) unsigned short g_WoTh[1048576], g_WoTl[1048576];
// attention operands
__device__ __align__(256) unsigned short g_Qh[4194304], g_Ql[4194304];   // [b,h,s,d] bf16
__device__ __align__(256) unsigned short g_Kh[4194304], g_Kl[4194304];   // [b,h,s,d] bf16
__device__ __align__(256) __half g_VT[4194304];                          // [b,h,d,s] fp16

// ======================== PTX helpers (base sm_80+ ISA only) ==============
__device__ __forceinline__ uint32_t smem_to_u32(const void* p) {
    uint32_t a;
    asm("{ .reg .u64 t; cvta.to.shared.u64 t, %1; cvt.u32.u64 %0, t; }"
        : "=r"(a) : "l"(p));
    return a;
}

#define CP_ASYNC16(sm, gp) \
    asm volatile("cp.async.cg.shared.global [%0], [%1], 16;" \
        :: "r"(sm), "l"(gp) : "memory")
#define CP_COMMIT() asm volatile("cp.async.commit_group;" ::: "memory")
#define CP_WAIT0()  asm volatile("cp.async.wait_group 0;" ::: "memory")

#define LDMATRIX_X4(r0, r1, r2, r3, addr) \
    asm volatile("ldmatrix.sync.aligned.m8n8.x4.shared.b16 {%0,%1,%2,%3}, [%4];" \
        : "=r"(r0), "=r"(r1), "=r"(r2), "=r"(r3) : "r"(addr))

#define MMA16816(C, A, B) \
    asm volatile("mma.sync.aligned.m16n8k16.row.col.f32.bf16.bf16.f32 " \
        "{%0,%1,%2,%3}, {%4,%5,%6,%7}, {%8,%9}, {%0,%1,%2,%3};" \
        : "+f"((C)[0]), "+f"((C)[1]), "+f"((C)[2]), "+f"((C)[3]) \
        : "r"((A)[0]), "r"((A)[1]), "r"((A)[2]), "r"((A)[3]), \
          "r"((B)[0]), "r"((B)[1]))

#define MMA16816F16(C, A, B) \
    asm volatile("mma.sync.aligned.m16n8k16.row.col.f32.f16.f16.f32 " \
        "{%0,%1,%2,%3}, {%4,%5,%6,%7}, {%8,%9}, {%0,%1,%2,%3};" \
        : "+f"((C)[0]), "+f"((C)[1]), "+f"((C)[2]), "+f"((C)[3]) \
        : "r"((A)[0]), "r"((A)[1]), "r"((A)[2]), "r"((A)[3]), \
          "r"((B)[0]), "r"((B)[1]))

// ===========================================================================
// split2: fp32 -> bf16 hi + lo, two sources batched via blockIdx.y
// ===========================================================================
struct SplitArgs {
    const float* src[2];
    unsigned short* hi[2];
    unsigned short* lo[2];
};
__global__ __launch_bounds__(256) void split2_kernel(SplitArgs a, int n4)
{
    const int w = blockIdx.y;
    int i = blockIdx.x * 256 + threadIdx.x;
    if (i >= n4) return;
    float4 v = ((const float4*)a.src[w])[i];
    float f[4] = {v.x, v.y, v.z, v.w};
#pragma unroll
    for (int j = 0; j < 4; j++) {
        __nv_bfloat16 h = __float2bfloat16_rn(f[j]);
        __nv_bfloat16 l = __float2bfloat16_rn(f[j] - __bfloat162float(h));
        a.hi[w][i * 4 + j] = __bfloat16_as_ushort(h);
        a.lo[w][i * 4 + j] = __bfloat16_as_ushort(l);
    }
}

// ===========================================================================
// transsplit4: W[k][n] fp32 -> WT_hi[n][k], WT_lo[n][k] bf16, 4 weights (z)
// ===========================================================================
struct TSArgs {
    const float* W[4];
    unsigned short* hi[4];
    unsigned short* lo[4];
};
__global__ __launch_bounds__(256) void transsplit4_kernel(TSArgs a)
{
    __shared__ unsigned short sh[64][68];
    __shared__ unsigned short sl[64][68];
    const int w = blockIdx.z;
    const float* W = a.W[w];
    const int k0 = blockIdx.y << 6, n0 = blockIdx.x << 6;
    const int r = threadIdx.x >> 4, c = (threadIdx.x & 15) << 2;
#pragma unroll
    for (int it = 0; it < 4; it++) {
        int row = r + it * 16;
        float4 v = *(const float4*)&W[(size_t)(k0 + row) * 1024 + n0 + c];
        float f[4] = {v.x, v.y, v.z, v.w};
#pragma unroll
        for (int j = 0; j < 4; j++) {
            __nv_bfloat16 h = __float2bfloat16_rn(f[j]);
            __nv_bfloat16 l = __float2bfloat16_rn(f[j] - __bfloat162float(h));
            sh[row][c + j] = __bfloat16_as_ushort(h);
            sl[row][c + j] = __bfloat16_as_ushort(l);
        }
    }
    __syncthreads();
#pragma unroll
    for (int it = 0; it < 4; it++) {
        int nn = r + it * 16;
#pragma unroll
        for (int j = 0; j < 4; j++) {
            a.hi[w][(size_t)(n0 + nn) * 1024 + k0 + c + j] = sh[c + j][nn];
            a.lo[w][(size_t)(n0 + nn) * 1024 + k0 + c + j] = sl[c + j][nn];
        }
    }
}

// ===========================================================================
// HMMA GEMM (bf16 3-product split), 128x128 tile, BK=64, double-buffered.
// R6 known-good: 256 threads, warp grid 4(M) x 2(N), warp tile 32x64.
// MODE 0: Q/K proj -> bf16 hi/lo scatter [b,h,s,d], (acc+bias)*scale
// MODE 1: out proj -> fp32 row-major, acc + bias + residual
// MODE 2: V proj -> fp16 transposed [b,h,d,s], acc + bias
// ===========================================================================
#define GT_ROW   72
#define GT_TILEB (128 * GT_ROW * 2)    // 18432
#define GT_STAGEB (4 * GT_TILEB)       // 73728
#define GT_SMEM_SZ (2 * GT_STAGEB)     // 147456

template <int MODE>
__global__ __launch_bounds__(256, 1)
void gemm_mma(const unsigned short* __restrict__ Ah, const unsigned short* __restrict__ Al,
              const unsigned short* __restrict__ Bh, const unsigned short* __restrict__ Bl,
              const float* __restrict__ bias, const float* __restrict__ residual,
              void* __restrict__ C0, void* __restrict__ C1, float scale)
{
    extern __shared__ char smem[];
    const uint32_t sb = smem_to_u32(smem);
    const int tid = threadIdx.x;
    const int wid = tid >> 5, lane = tid & 31;
    const int wm = wid & 3, wn = wid >> 2;
    const int m0 = blockIdx.y * 128, n0 = blockIdx.x * 128;

    const int crow = tid >> 1;
    const int cseg = (tid & 1) * 4;
    const unsigned short* gsrc[4] = {
        Ah + (size_t)(m0 + crow) * 1024, Al + (size_t)(m0 + crow) * 1024,
        Bh + (size_t)(n0 + crow) * 1024, Bl + (size_t)(n0 + crow) * 1024};
    const uint32_t srow = crow * (GT_ROW * 2) + cseg * 16;

    auto load_stage = [&](int stg, int k0) {
#pragma unroll
        for (int tile = 0; tile < 4; tile++) {
            const unsigned short* g = gsrc[tile] + k0 + cseg * 8;
            uint32_t s = sb + stg * GT_STAGEB + tile * GT_TILEB + srow;
#pragma unroll
            for (int i = 0; i < 4; i++)
                CP_ASYNC16(s + i * 16, g + i * 8);
        }
        CP_COMMIT();
    };

    float acc[2][8][4];
#pragma unroll
    for (int mt = 0; mt < 2; mt++)
#pragma unroll
        for (int nt = 0; nt < 8; nt++)
#pragma unroll
            for (int j = 0; j < 4; j++) acc[mt][nt][j] = 0.f;

    const int lg = lane >> 3, lr = lane & 7;
    const int rowoff = (lg & 1) * 8 + lr;
    const uint32_t kquad = (lg >> 1) * 16;

    load_stage(0, 0);
    CP_WAIT0();
    __syncthreads();

    for (int t = 0; t < 16; t++) {
        const int buf = t & 1;
        if (t + 1 < 16) load_stage(buf ^ 1, (t + 1) * 64);

        const uint32_t stg = sb + buf * GT_STAGEB;
#pragma unroll
        for (int ks = 0; ks < 4; ks++) {
            const uint32_t kb = ks * 32 + kquad;
            uint32_t ah[2][4], al[2][4];
#pragma unroll
            for (int mt = 0; mt < 2; mt++) {
                uint32_t r = (wm * 32 + mt * 16 + rowoff) * (GT_ROW * 2) + kb;
                LDMATRIX_X4(ah[mt][0], ah[mt][1], ah[mt][2], ah[mt][3], stg + r);
                LDMATRIX_X4(al[mt][0], al[mt][1], al[mt][2], al[mt][3],
                            stg + GT_TILEB + r);
            }
            uint32_t bh[8][2], bl[8][2];
#pragma unroll
            for (int p = 0; p < 4; p++) {
                uint32_t r = (wn * 64 + p * 16 + rowoff) * (GT_ROW * 2) + kb;
                LDMATRIX_X4(bh[2 * p][0], bh[2 * p + 1][0],
                            bh[2 * p][1], bh[2 * p + 1][1],
                            stg + 2 * GT_TILEB + r);
                LDMATRIX_X4(bl[2 * p][0], bl[2 * p + 1][0],
                            bl[2 * p][1], bl[2 * p + 1][1],
                            stg + 3 * GT_TILEB + r);
            }
#pragma unroll
            for (int mt = 0; mt < 2; mt++)
#pragma unroll
                for (int nt = 0; nt < 8; nt++) {
                    MMA16816(acc[mt][nt], ah[mt], bh[nt]);
                    MMA16816(acc[mt][nt], ah[mt], bl[nt]);
                    MMA16816(acc[mt][nt], al[mt], bh[nt]);
                }
        }
        if (t + 1 < 16) CP_WAIT0();
        __syncthreads();
    }

    // ---- epilogue ----
    const int erow = lane >> 2;
    const int ecol = (lane & 3) * 2;
#pragma unroll
    for (int mt = 0; mt < 2; mt++) {
#pragma unroll
        for (int nt = 0; nt < 8; nt++) {
            const int n = n0 + wn * 64 + nt * 8 + ecol;
            const float b0 = bias[n], b1 = bias[n + 1];
#pragma unroll
            for (int half = 0; half < 2; half++) {
                const int m = m0 + wm * 32 + mt * 16 + erow + half * 8;
                float v0 = acc[mt][nt][half * 2 + 0] + b0;
                float v1 = acc[mt][nt][half * 2 + 1] + b1;
                if (MODE == 0) {
                    v0 *= scale; v1 *= scale;
                    const int bb = m >> 10, s = m & 1023, hh = n >> 6, d = n & 63;
                    const size_t idx = ((size_t)(bb * Hc + hh) * Sc + s) * Dk + d;
                    __nv_bfloat16 h0 = __float2bfloat16_rn(v0);
                    __nv_bfloat16 h1 = __float2bfloat16_rn(v1);
                    __nv_bfloat16 l0 = __float2bfloat16_rn(v0 - __bfloat162float(h0));
                    __nv_bfloat16 l1 = __float2bfloat16_rn(v1 - __bfloat162float(h1));
                    ushort2 uh; uh.x = __bfloat16_as_ushort(h0); uh.y = __bfloat16_as_ushort(h1);
                    ushort2 ul; ul.x = __bfloat16_as_ushort(l0); ul.y = __bfloat16_as_ushort(l1);
                    *(ushort2*)&((unsigned short*)C0)[idx] = uh;
                    *(ushort2*)&((unsigned short*)C1)[idx] = ul;
                } else if (MODE == 2) {
                    const int bb = m >> 10, s = m & 1023, hh = n >> 6, d = n & 63;
                    const size_t idx = ((size_t)(bb * Hc + hh) * Dk + d) * Sc + s;
                    ((__half*)C0)[idx] = __float2half_rn(v0);
                    ((__half*)C0)[idx + Sc] = __float2half_rn(v1);
                } else {
                    const size_t idx = (size_t)m * 1024 + n;
                    float2 r = *(const float2*)&residual[idx];
                    float2 v; v.x = v0 + r.x; v.y = v1 + r.y;
                    *(float2*)&((float*)C0)[idx] = v;
                }
            }
        }
    }
}

// ===========================================================================
// scores kernel: S = Q.K^T (bf16 split, K=64), mask fused.
// R6 known-good: 256 threads, warp grid 4x2. grid (8 ntile, 8 mtile, 64 bh).
// ===========================================================================
#define SC_SMEM_SZ (4 * GT_TILEB)   // 73728

__global__ __launch_bounds__(256, 1)
void scores_kernel(const int* __restrict__ mask, float* __restrict__ S)
{
    extern __shared__ char smem[];
    const uint32_t sb = smem_to_u32(smem);
    const int tid = threadIdx.x;
    const int wid = tid >> 5, lane = tid & 31;
    const int wm = wid & 3, wn = wid >> 2;
    const int bh = blockIdx.z, b = bh >> 4;
    const int m0 = blockIdx.y * 128, n0 = blockIdx.x * 128;

    const size_t base = (size_t)bh * (Sc * Dk);
    const int crow = tid >> 1;
    const int chalf = tid & 1;
    const unsigned short* gsrc[4] = {
        g_Qh + base + (size_t)(m0 + crow) * 64 + chalf * 32,
        g_Ql + base + (size_t)(m0 + crow) * 64 + chalf * 32,
        g_Kh + base + (size_t)(n0 + crow) * 64 + chalf * 32,
        g_Kl + base + (size_t)(n0 + crow) * 64 + chalf * 32};
    const uint32_t srow = crow * (GT_ROW * 2) + chalf * 64;

#pragma unroll
    for (int tile = 0; tile < 4; tile++) {
        uint32_t s = sb + tile * GT_TILEB + srow;
#pragma unroll
        for (int i = 0; i < 4; i++)
            CP_ASYNC16(s + i * 16, gsrc[tile] + i * 8);
    }
    CP_COMMIT();

    float acc[2][8][4];
#pragma unroll
    for (int mt = 0; mt < 2; mt++)
#pragma unroll
        for (int nt = 0; nt < 8; nt++)
#pragma unroll
            for (int j = 0; j < 4; j++) acc[mt][nt][j] = 0.f;

    const int lg = lane >> 3, lr = lane & 7;
    const int rowoff = (lg & 1) * 8 + lr;
    const uint32_t kquad = (lg >> 1) * 16;

    CP_WAIT0();
    __syncthreads();

#pragma unroll
    for (int ks = 0; ks < 4; ks++) {
        const uint32_t kb = ks * 32 + kquad;
        uint32_t ah[2][4], al[2][4];
#pragma unroll
        for (int mt = 0; mt < 2; mt++) {
            uint32_t r = (wm * 32 + mt * 16 + rowoff) * (GT_ROW * 2) + kb;
            LDMATRIX_X4(ah[mt][0], ah[mt][1], ah[mt][2], ah[mt][3], sb + r);
            LDMATRIX_X4(al[mt][0], al[mt][1], al[mt][2], al[mt][3],
                        sb + GT_TILEB + r);
        }
        uint32_t bhf[8][2], blf[8][2];
#pragma unroll
        for (int p = 0; p < 4; p++) {
            uint32_t r = (wn * 64 + p * 16 + rowoff) * (GT_ROW * 2) + kb;
            LDMATRIX_X4(bhf[2 * p][0], bhf[2 * p + 1][0],
                        bhf[2 * p][1], bhf[2 * p + 1][1],
                        sb + 2 * GT_TILEB + r);
            LDMATRIX_X4(blf[2 * p][0], blf[2 * p + 1][0],
                        blf[2 * p][1], blf[2 * p + 1][1],
                        sb + 3 * GT_TILEB + r);
        }
#pragma unroll
        for (int mt = 0; mt < 2; mt++)
#pragma unroll
            for (int nt = 0; nt < 8; nt++) {
                MMA16816(acc[mt][nt], ah[mt], bhf[nt]);
                MMA16816(acc[mt][nt], ah[mt], blf[nt]);
                MMA16816(acc[mt][nt], al[mt], bhf[nt]);
            }
    }

    // epilogue: mask + store fp32 scores
    const int erow = lane >> 2;
    const int ecol = (lane & 3) * 2;
    float* Sb = S + (size_t)bh * Sc * Sc;
#pragma unroll
    for (int mt = 0; mt < 2; mt++) {
#pragma unroll
        for (int nt = 0; nt < 8; nt++) {
            const int n = n0 + wn * 64 + nt * 8 + ecol;
            const bool mk0 = (mask[b * Sc + n] == 0);
            const bool mk1 = (mask[b * Sc + n + 1] == 0);
#pragma unroll
            for (int half = 0; half < 2; half++) {
                const int m = m0 + wm * 32 + mt * 16 + erow + half * 8;
                float2 v;
                v.x = mk0 ? -1e9f : acc[mt][nt][half * 2 + 0];
                v.y = mk1 ? -1e9f : acc[mt][nt][half * 2 + 1];
                *(float2*)&Sb[(size_t)m * Sc + n] = v;
            }
        }
    }
}

// ===========================================================================
// FUSED softmax + ctx kernel.
// Block = 32 q-rows of one (b,h). 256 threads, 2 CTAs/SM.
// Phase 1: softmax on raw scores in gmem (in-place -> fp32 attn output),
//          fp16 probs parked in smem (row stride 2064B, ldmatrix-clean).
// Phase 2: ctx = P(smem) . V(gmem, cp.async double-buffered) via fp16 MMA,
//          32x64 output -> bf16 hi/lo split.
// grid (32 qtile, 64 bh).
// ===========================================================================
#define FX_PROWB 2064                          // 1024 halfs + 8 pad (16B shift/row)
#define FX_PBYTES (32 * FX_PROWB)              // 66048
#define FX_VROWB 144
#define FX_VTILEB (64 * FX_VROWB)              // 9216
#define FX_SMEM (FX_PBYTES + 2 * FX_VTILEB)    // 84480

__global__ __launch_bounds__(256, 2)
void softmax_ctx_kernel(float* __restrict__ S,
                        unsigned short* __restrict__ Chi,
                        unsigned short* __restrict__ Clo)
{
    extern __shared__ char smem[];
    const uint32_t sb = smem_to_u32(smem);
    const uint32_t sbV = sb + FX_PBYTES;
    const int tid = threadIdx.x;
    const int wid = tid >> 5, lane = tid & 31;
    const int bh = blockIdx.y, b = bh >> 4, h = bh & 15;
    const int m0 = blockIdx.x * 32;

    float* Sb = S + ((size_t)bh * Sc + m0) * Sc;
    const __half* Vb = g_VT + (size_t)bh * (Dk * Sc);

    // V tile loader: 64 rows(d) x 64 halfs(k), 2 threads/row on first 128 thr
    auto loadV = [&](int stg, int kt) {
        if (tid < 128) {
            const int brow = tid >> 1, bhalf = tid & 1;
            const __half* gbp = Vb + (size_t)brow * 1024 + kt * 64 + bhalf * 32;
            uint32_t sB = sbV + stg * FX_VTILEB + brow * FX_VROWB + bhalf * 64;
#pragma unroll
            for (int i = 0; i < 4; i++)
                CP_ASYNC16(sB + i * 16, gbp + i * 8);
        }
        CP_COMMIT();
    };

    // prefetch V tile 0 (independent of P)
    loadV(0, 0);

    // ---- phase 1: softmax, one warp handles 4 rows ----
#pragma unroll
    for (int r4 = 0; r4 < 4; r4++) {
        const int row = wid * 4 + r4;
        float* rp = Sb + (size_t)row * Sc;
        float4 v[8];
        float mx = -3.4e38f;
#pragma unroll
        for (int i = 0; i < 8; i++) {
            v[i] = *(const float4*)&rp[lane * 4 + i * 128];
            mx = fmaxf(mx, fmaxf(fmaxf(v[i].x, v[i].y), fmaxf(v[i].z, v[i].w)));
        }
#pragma unroll
        for (int o = 16; o; o >>= 1) mx = fmaxf(mx, __shfl_xor_sync(~0u, mx, o));
        float sum = 0.f;
#pragma unroll
        for (int i = 0; i < 8; i++) {
            v[i].x = expf(v[i].x - mx); v[i].y = expf(v[i].y - mx);
            v[i].z = expf(v[i].z - mx); v[i].w = expf(v[i].w - mx);
            sum += (v[i].x + v[i].y) + (v[i].z + v[i].w);
        }
#pragma unroll
        for (int o = 16; o; o >>= 1) sum += __shfl_xor_sync(~0u, sum, o);
        const float inv = 1.f / sum;
        const uint32_t srow = sb + row * FX_PROWB;
#pragma unroll
        for (int i = 0; i < 8; i++) {
            float4 p;
            p.x = v[i].x * inv; p.y = v[i].y * inv;
            p.z = v[i].z * inv; p.w = v[i].w * inv;
            *(float4*)&rp[lane * 4 + i * 128] = p;
            __half2 h0 = __floats2half2_rn(p.x, p.y);
            __half2 h1 = __floats2half2_rn(p.z, p.w);
            asm volatile("st.shared.v2.b32 [%0], {%1, %2};"
                :: "r"(srow + (lane * 4 + i * 128) * 2),
                   "r"(*(uint32_t*)&h0), "r"(*(uint32_t*)&h1) : "memory");
        }
    }
    __syncthreads();     // P smem complete

    // ---- phase 2: ctx = P . V ----
    const int wm = wid & 1, wn = wid >> 1;    // 2(m) x 4(n) warp grid
    float acc[2][4];
#pragma unroll
    for (int nt = 0; nt < 2; nt++)
#pragma unroll
        for (int j = 0; j < 4; j++) acc[nt][j] = 0.f;

    const int lg = lane >> 3, lr = lane & 7;
    const int rowoff = (lg & 1) * 8 + lr;
    const uint32_t kquad = (lg >> 1) * 16;

    CP_WAIT0();          // V tile 0 ready
    __syncthreads();

    for (int t = 0; t < 16; t++) {
        const int buf = t & 1;
        if (t + 1 < 16) loadV(buf ^ 1, t + 1);

        const uint32_t sV = sbV + buf * FX_VTILEB;
#pragma unroll
        for (int ks = 0; ks < 4; ks++) {
            const uint32_t kb = ks * 32 + kquad;
            uint32_t af[4];
            {
                uint32_t r = sb + (wm * 16 + rowoff) * FX_PROWB + t * 128 + kb;
                LDMATRIX_X4(af[0], af[1], af[2], af[3], r);
            }
            uint32_t bf[2][2];
            {
                uint32_t r = sV + (wn * 16 + rowoff) * FX_VROWB + kb;
                LDMATRIX_X4(bf[0][0], bf[1][0], bf[0][1], bf[1][1], r);
            }
            MMA16816F16(acc[0], af, bf[0]);
            MMA16816F16(acc[1], af, bf[1]);
        }
        if (t + 1 < 16) CP_WAIT0();
        __syncthreads();
    }

    // ---- epilogue: bf16 hi/lo split -> g_ch/g_cl ----
    const int erow = lane >> 2;
    const int ecol = (lane & 3) * 2;
#pragma unroll
    for (int nt = 0; nt < 2; nt++) {
        const int d = wn * 16 + nt * 8 + ecol;
#pragma unroll
        for (int half = 0; half < 2; half++) {
            const int q = m0 + wm * 16 + erow + half * 8;
            float v0 = acc[nt][half * 2 + 0];
            float v1 = acc[nt][half * 2 + 1];
            __nv_bfloat16 h0 = __float2bfloat16_rn(v0);
            __nv_bfloat16 h1 = __float2bfloat16_rn(v1);
            __nv_bfloat16 l0 = __float2bfloat16_rn(v0 - __bfloat162float(h0));
            __nv_bfloat16 l1 = __float2bfloat16_rn(v1 - __bfloat162float(h1));
            const size_t idx = ((size_t)(b * Sc) + q) * 1024 + h * Dk + d;
            ushort2 uh; uh.x = __bfloat16_as_ushort(h0); uh.y = __bfloat16_as_ushort(h1);
            ushort2 ul; ul.x = __bfloat16_as_ushort(l0); ul.y = __bfloat16_as_ushort(l1);
            *(ushort2*)&Chi[idx] = uh;
            *(ushort2*)&Clo[idx] = ul;
        }
    }
}

// ===========================================================================
// LayerNorm
// ===========================================================================
__global__ __launch_bounds__(256) void ln_kernel(
    const float* __restrict__ X, const float* __restrict__ gamma,
    const float* __restrict__ beta, float* __restrict__ out)
{
    __shared__ float red1[8];
    __shared__ float red2[8];
    const int row = blockIdx.x;
    const int tid = threadIdx.x;
    const float* x = X + (size_t)row * 1024;

    float v[4];
    float s = 0.f;
#pragma unroll
    for (int i = 0; i < 4; i++) { v[i] = x[tid + i * 256]; s += v[i]; }
#pragma unroll
    for (int o = 16; o; o >>= 1) s += __shfl_xor_sync(~0u, s, o);
    if ((tid & 31) == 0) red1[tid >> 5] = s;
    __syncthreads();
    if (tid < 32) {
        float t = (tid < 8) ? red1[tid] : 0.f;
#pragma unroll
        for (int o = 4; o; o >>= 1) t += __shfl_xor_sync(~0u, t, o);
        if (tid == 0) red1[0] = t;
    }
    __syncthreads();
    const float mu = red1[0] * (1.f / 1024.f);

    float ss = 0.f;
#pragma unroll
    for (int i = 0; i < 4; i++) { float d = v[i] - mu; ss += d * d; }
#pragma unroll
    for (int o = 16; o; o >>= 1) ss += __shfl_xor_sync(~0u, ss, o);
    if ((tid & 31) == 0) red2[tid >> 5] = ss;
    __syncthreads();
    if (tid < 32) {
        float t = (tid < 8) ? red2[tid] : 0.f;
#pragma unroll
        for (int o = 4; o; o >>= 1) t += __shfl_xor_sync(~0u, t, o);
        if (tid == 0) red2[0] = t;
    }
    __syncthreads();
    const float var = red2[0] * (1.f / 1024.f);
    const float rs = rsqrtf(var + 1e-5f);

#pragma unroll
    for (int i = 0; i < 4; i++) {
        const int c = tid + i * 256;
        out[(size_t)row * 1024 + c] = (v[i] - mu) * rs * gamma[c] + beta[c];
    }
}

// ===========================================================================
// Launch
// ===========================================================================
extern "C" void kernel_launch(void* const* d_in, const int* in_sizes, int n_in,
                              void* d_out, int out_size)
{
    const float* memory = (const float*)d_in[0];
    const float* dec    = (const float*)d_in[1];
    const int*   mask   = (const int*)d_in[2];
    const float* Wq = (const float*)d_in[3];
    const float* bq = (const float*)d_in[4];
    const float* Wk = (const float*)d_in[5];
    const float* bk = (const float*)d_in[6];
    const float* Wv = (const float*)d_in[7];
    const float* bv = (const float*)d_in[8];
    const float* Wo = (const float*)d_in[9];
    const float* bo = (const float*)d_in[10];
    const float* gamma = (const float*)d_in[11];
    const float* beta  = (const float*)d_in[12];

    float* out  = (float*)d_out;
    float* attn = out + (size_t)Bc * Sc * Dm;

    void *pX, *pmh, *pml, *pdh, *pdl, *pch, *pcl;
    cudaGetSymbolAddress(&pX, g_X);
    cudaGetSymbolAddress(&pmh, g_mh); cudaGetSymbolAddress(&pml, g_ml);
    cudaGetSymbolAddress(&pdh, g_dh); cudaGetSymbolAddress(&pdl, g_dl);
    cudaGetSymbolAddress(&pch, g_ch); cudaGetSymbolAddress(&pcl, g_cl);
    void *pqh, *pql, *pkh, *pkl, *pvh, *pvl, *poh, *pol;
    cudaGetSymbolAddress(&pqh, g_WqTh); cudaGetSymbolAddress(&pql, g_WqTl);
    cudaGetSymbolAddress(&pkh, g_WkTh); cudaGetSymbolAddress(&pkl, g_WkTl);
    cudaGetSymbolAddress(&pvh, g_WvTh); cudaGetSymbolAddress(&pvl, g_WvTl);
    cudaGetSymbolAddress(&poh, g_WoTh); cudaGetSymbolAddress(&pol, g_WoTl);
    void *pQh, *pQl, *pKh, *pKl, *pVT;
    cudaGetSymbolAddress(&pQh, g_Qh); cudaGetSymbolAddress(&pQl, g_Ql);
    cudaGetSymbolAddress(&pKh, g_Kh); cudaGetSymbolAddress(&pKl, g_Kl);
    cudaGetSymbolAddress(&pVT, g_VT);

    const int NACT4 = Bc * Sc * Dm / 4;

    // ---- prep (2 launches) ----
    SplitArgs sa;
    sa.src[0] = memory; sa.hi[0] = (unsigned short*)pmh; sa.lo[0] = (unsigned short*)pml;
    sa.src[1] = dec;    sa.hi[1] = (unsigned short*)pdh; sa.lo[1] = (unsigned short*)pdl;
    split2_kernel<<<dim3(NACT4 / 256, 2), 256>>>(sa, NACT4);

    TSArgs ta;
    ta.W[0] = Wq; ta.hi[0] = (unsigned short*)pqh; ta.lo[0] = (unsigned short*)pql;
    ta.W[1] = Wk; ta.hi[1] = (unsigned short*)pkh; ta.lo[1] = (unsigned short*)pkl;
    ta.W[2] = Wv; ta.hi[2] = (unsigned short*)pvh; ta.lo[2] = (unsigned short*)pvl;
    ta.W[3] = Wo; ta.hi[3] = (unsigned short*)poh; ta.lo[3] = (unsigned short*)pol;
    transsplit4_kernel<<<dim3(16, 16, 4), 256>>>(ta);

    // ---- projections (R6 known-good config) ----
    cudaFuncSetAttribute(gemm_mma<0>, cudaFuncAttributeMaxDynamicSharedMemorySize, GT_SMEM_SZ);
    cudaFuncSetAttribute(gemm_mma<1>, cudaFuncAttributeMaxDynamicSharedMemorySize, GT_SMEM_SZ);
    cudaFuncSetAttribute(gemm_mma<2>, cudaFuncAttributeMaxDynamicSharedMemorySize, GT_SMEM_SZ);
    const dim3 gg(8, 32), gt(256);
    gemm_mma<0><<<gg, gt, GT_SMEM_SZ>>>((unsigned short*)pmh, (unsigned short*)pml,
                                        (unsigned short*)pqh, (unsigned short*)pql,
                                        bq, nullptr, pQh, pQl, 0.125f);
    gemm_mma<0><<<gg, gt, GT_SMEM_SZ>>>((unsigned short*)pmh, (unsigned short*)pml,
                                        (unsigned short*)pkh, (unsigned short*)pkl,
                                        bk, nullptr, pKh, pKl, 1.0f);
    gemm_mma<2><<<gg, gt, GT_SMEM_SZ>>>((unsigned short*)pdh, (unsigned short*)pdl,
                                        (unsigned short*)pvh, (unsigned short*)pvl,
                                        bv, nullptr, pVT, nullptr, 1.0f);

    // ---- attention: scores -> fused softmax+ctx ----
    cudaFuncSetAttribute(scores_kernel, cudaFuncAttributeMaxDynamicSharedMemorySize, SC_SMEM_SZ);
    scores_kernel<<<dim3(8, 8, Bc * Hc), 256, SC_SMEM_SZ>>>(mask, attn);

    cudaFuncSetAttribute(softmax_ctx_kernel, cudaFuncAttributeMaxDynamicSharedMemorySize, FX_SMEM);
    softmax_ctx_kernel<<<dim3(32, Bc * Hc), 256, FX_SMEM>>>(attn,
                                                            (unsigned short*)pch,
                                                            (unsigned short*)pcl);

    // ---- output projection + residual, then LayerNorm ----
    gemm_mma<1><<<gg, gt, GT_SMEM_SZ>>>((unsigned short*)pch, (unsigned short*)pcl,
                                        (unsigned short*)poh, (unsigned short*)pol,
                                        bo, memory, pX, nullptr, 1.0f);
    ln_kernel<<<Bc * Sc, 256>>>((const float*)pX, gamma, beta, out);
}

// round 12
// speedup vs baseline: 1.0114x; 1.0073x over previous
#include <cuda_runtime.h>
#include <cuda_bf16.h>
#include <cuda_fp16.h>
#include <cstdint>
#include <math.h>

#define Bc 4
#define Sc 1024
#define Dm 1024
#define Hc 16
#define Dk 64

// -------- device scratch (allocation-free: static device globals) --------
__device__ float g_X[Bc * Sc * Dm];        // pre-LN activations

// bf16 split scratch
__device__ __align__(256) unsigned short g_mh[4194304], g_ml[4194304];   // memory hi/lo
__device__ __align__(256) unsigned short g_dh[4194304], g_dl[4194304];   // decoder hi/lo
__device__ __align__(256) unsigned short g_ch[4194304], g_cl[4194304];   // ctx hi/lo
__device__ __align__(256) unsigned short g_WqTh[1048576], g_WqTl[1048576];
__device__ __align__(256) unsigned short g_WkTh[1048576], g_WkTl[1048576];
__device__ __align__(256) unsigned short g_WvTh[1048576], g_WvTl[1048576];
__device__ __align__(256) unsigned short g_WoTh[1048576], g_WoTl[1048576];
// attention operands
__device__ __align__(256) unsigned short g_Qh[4194304], g_Ql[4194304];   // [b,h,s,d] bf16
__device__ __align__(256) unsigned short g_Kh[4194304], g_Kl[4194304];   // [b,h,s,d] bf16
__device__ __align__(256) __half g_VT[4194304];                          // [b,h,d,s] fp16

// ======================== PTX helpers (base sm_80+ ISA only) ==============
__device__ __forceinline__ uint32_t smem_to_u32(const void* p) {
    uint32_t a;
    asm("{ .reg .u64 t; cvta.to.shared.u64 t, %1; cvt.u32.u64 %0, t; }"
        : "=r"(a) : "l"(p));
    return a;
}

#define CP_ASYNC16(sm, gp) \
    asm volatile("cp.async.cg.shared.global [%0], [%1], 16;" \
        :: "r"(sm), "l"(gp) : "memory")
#define CP_COMMIT() asm volatile("cp.async.commit_group;" ::: "memory")
#define CP_WAIT0()  asm volatile("cp.async.wait_group 0;" ::: "memory")

#define LDMATRIX_X4(r0, r1, r2, r3, addr) \
    asm volatile("ldmatrix.sync.aligned.m8n8.x4.shared.b16 {%0,%1,%2,%3}, [%4];" \
        : "=r"(r0), "=r"(r1), "=r"(r2), "=r"(r3) : "r"(addr))

#define MMA16816(C, A, B) \
    asm volatile("mma.sync.aligned.m16n8k16.row.col.f32.bf16.bf16.f32 " \
        "{%0,%1,%2,%3}, {%4,%5,%6,%7}, {%8,%9}, {%0,%1,%2,%3};" \
        : "+f"((C)[0]), "+f"((C)[1]), "+f"((C)[2]), "+f"((C)[3]) \
        : "r"((A)[0]), "r"((A)[1]), "r"((A)[2]), "r"((A)[3]), \
          "r"((B)[0]), "r"((B)[1]))

#define MMA16816F16(C, A, B) \
    asm volatile("mma.sync.aligned.m16n8k16.row.col.f32.f16.f16.f32 " \
        "{%0,%1,%2,%3}, {%4,%5,%6,%7}, {%8,%9}, {%0,%1,%2,%3};" \
        : "+f"((C)[0]), "+f"((C)[1]), "+f"((C)[2]), "+f"((C)[3]) \
        : "r"((A)[0]), "r"((A)[1]), "r"((A)[2]), "r"((A)[3]), \
          "r"((B)[0]), "r"((B)[1]))

// ===========================================================================
// split2: fp32 -> bf16 hi + lo, two sources batched via blockIdx.y
// ===========================================================================
struct SplitArgs {
    const float* src[2];
    unsigned short* hi[2];
    unsigned short* lo[2];
};
__global__ __launch_bounds__(256) void split2_kernel(SplitArgs a, int n4)
{
    const int w = blockIdx.y;
    int i = blockIdx.x * 256 + threadIdx.x;
    if (i >= n4) return;
    float4 v = ((const float4*)a.src[w])[i];
    float f[4] = {v.x, v.y, v.z, v.w};
#pragma unroll
    for (int j = 0; j < 4; j++) {
        __nv_bfloat16 h = __float2bfloat16_rn(f[j]);
        __nv_bfloat16 l = __float2bfloat16_rn(f[j] - __bfloat162float(h));
        a.hi[w][i * 4 + j] = __bfloat16_as_ushort(h);
        a.lo[w][i * 4 + j] = __bfloat16_as_ushort(l);
    }
}

// ===========================================================================
// transsplit4: W[k][n] fp32 -> WT_hi[n][k], WT_lo[n][k] bf16, 4 weights (z)
// ===========================================================================
struct TSArgs {
    const float* W[4];
    unsigned short* hi[4];
    unsigned short* lo[4];
};
__global__ __launch_bounds__(256) void transsplit4_kernel(TSArgs a)
{
    __shared__ unsigned short sh[64][68];
    __shared__ unsigned short sl[64][68];
    const int w = blockIdx.z;
    const float* W = a.W[w];
    const int k0 = blockIdx.y << 6, n0 = blockIdx.x << 6;
    const int r = threadIdx.x >> 4, c = (threadIdx.x & 15) << 2;
#pragma unroll
    for (int it = 0; it < 4; it++) {
        int row = r + it * 16;
        float4 v = *(const float4*)&W[(size_t)(k0 + row) * 1024 + n0 + c];
        float f[4] = {v.x, v.y, v.z, v.w};
#pragma unroll
        for (int j = 0; j < 4; j++) {
            __nv_bfloat16 h = __float2bfloat16_rn(f[j]);
            __nv_bfloat16 l = __float2bfloat16_rn(f[j] - __bfloat162float(h));
            sh[row][c + j] = __bfloat16_as_ushort(h);
            sl[row][c + j] = __bfloat16_as_ushort(l);
        }
    }
    __syncthreads();
#pragma unroll
    for (int it = 0; it < 4; it++) {
        int nn = r + it * 16;
#pragma unroll
        for (int j = 0; j < 4; j++) {
            a.hi[w][(size_t)(n0 + nn) * 1024 + k0 + c + j] = sh[c + j][nn];
            a.lo[w][(size_t)(n0 + nn) * 1024 + k0 + c + j] = sl[c + j][nn];
        }
    }
}

// ===========================================================================
// HMMA GEMM (bf16 3-product split), 128x128 tile, BK=64, double-buffered.
// R6 known-good: 256 threads, warp grid 4(M) x 2(N), warp tile 32x64.
// MODE 0: Q/K proj -> bf16 hi/lo scatter [b,h,s,d], (acc+bias)*scale
// MODE 1: out proj -> fp32 row-major, acc + bias + residual
// MODE 2: V proj -> fp16 transposed [b,h,d,s], acc + bias
// ===========================================================================
#define GT_ROW   72
#define GT_TILEB (128 * GT_ROW * 2)    // 18432
#define GT_STAGEB (4 * GT_TILEB)       // 73728
#define GT_SMEM_SZ (2 * GT_STAGEB)     // 147456

template <int MODE>
__global__ __launch_bounds__(256, 1)
void gemm_mma(const unsigned short* __restrict__ Ah, const unsigned short* __restrict__ Al,
              const unsigned short* __restrict__ Bh, const unsigned short* __restrict__ Bl,
              const float* __restrict__ bias, const float* __restrict__ residual,
              void* __restrict__ C0, void* __restrict__ C1, float scale)
{
    extern __shared__ char smem[];
    const uint32_t sb = smem_to_u32(smem);
    const int tid = threadIdx.x;
    const int wid = tid >> 5, lane = tid & 31;
    const int wm = wid & 3, wn = wid >> 2;
    const int m0 = blockIdx.y * 128, n0 = blockIdx.x * 128;

    const int crow = tid >> 1;
    const int cseg = (tid & 1) * 4;
    const unsigned short* gsrc[4] = {
        Ah + (size_t)(m0 + crow) * 1024, Al + (size_t)(m0 + crow) * 1024,
        Bh + (size_t)(n0 + crow) * 1024, Bl + (size_t)(n0 + crow) * 1024};
    const uint32_t srow = crow * (GT_ROW * 2) + cseg * 16;

    auto load_stage = [&](int stg, int k0) {
#pragma unroll
        for (int tile = 0; tile < 4; tile++) {
            const unsigned short* g = gsrc[tile] + k0 + cseg * 8;
            uint32_t s = sb + stg * GT_STAGEB + tile * GT_TILEB + srow;
#pragma unroll
            for (int i = 0; i < 4; i++)
                CP_ASYNC16(s + i * 16, g + i * 8);
        }
        CP_COMMIT();
    };

    float acc[2][8][4];
#pragma unroll
    for (int mt = 0; mt < 2; mt++)
#pragma unroll
        for (int nt = 0; nt < 8; nt++)
#pragma unroll
            for (int j = 0; j < 4; j++) acc[mt][nt][j] = 0.f;

    const int lg = lane >> 3, lr = lane & 7;
    const int rowoff = (lg & 1) * 8 + lr;
    const uint32_t kquad = (lg >> 1) * 16;

    load_stage(0, 0);
    CP_WAIT0();
    __syncthreads();

    for (int t = 0; t < 16; t++) {
        const int buf = t & 1;
        if (t + 1 < 16) load_stage(buf ^ 1, (t + 1) * 64);

        const uint32_t stg = sb + buf * GT_STAGEB;
#pragma unroll
        for (int ks = 0; ks < 4; ks++) {
            const uint32_t kb = ks * 32 + kquad;
            uint32_t ah[2][4], al[2][4];
#pragma unroll
            for (int mt = 0; mt < 2; mt++) {
                uint32_t r = (wm * 32 + mt * 16 + rowoff) * (GT_ROW * 2) + kb;
                LDMATRIX_X4(ah[mt][0], ah[mt][1], ah[mt][2], ah[mt][3], stg + r);
                LDMATRIX_X4(al[mt][0], al[mt][1], al[mt][2], al[mt][3],
                            stg + GT_TILEB + r);
            }
            uint32_t bh[8][2], bl[8][2];
#pragma unroll
            for (int p = 0; p < 4; p++) {
                uint32_t r = (wn * 64 + p * 16 + rowoff) * (GT_ROW * 2) + kb;
                LDMATRIX_X4(bh[2 * p][0], bh[2 * p + 1][0],
                            bh[2 * p][1], bh[2 * p + 1][1],
                            stg + 2 * GT_TILEB + r);
                LDMATRIX_X4(bl[2 * p][0], bl[2 * p + 1][0],
                            bl[2 * p][1], bl[2 * p + 1][1],
                            stg + 3 * GT_TILEB + r);
            }
#pragma unroll
            for (int mt = 0; mt < 2; mt++)
#pragma unroll
                for (int nt = 0; nt < 8; nt++) {
                    MMA16816(acc[mt][nt], ah[mt], bh[nt]);
                    MMA16816(acc[mt][nt], ah[mt], bl[nt]);
                    MMA16816(acc[mt][nt], al[mt], bh[nt]);
                }
        }
        if (t + 1 < 16) CP_WAIT0();
        __syncthreads();
    }

    // ---- epilogue ----
    const int erow = lane >> 2;
    const int ecol = (lane & 3) * 2;
#pragma unroll
    for (int mt = 0; mt < 2; mt++) {
#pragma unroll
        for (int nt = 0; nt < 8; nt++) {
            const int n = n0 + wn * 64 + nt * 8 + ecol;
            const float b0 = bias[n], b1 = bias[n + 1];
#pragma unroll
            for (int half = 0; half < 2; half++) {
                const int m = m0 + wm * 32 + mt * 16 + erow + half * 8;
                float v0 = acc[mt][nt][half * 2 + 0] + b0;
                float v1 = acc[mt][nt][half * 2 + 1] + b1;
                if (MODE == 0) {
                    v0 *= scale; v1 *= scale;
                    const int bb = m >> 10, s = m & 1023, hh = n >> 6, d = n & 63;
                    const size_t idx = ((size_t)(bb * Hc + hh) * Sc + s) * Dk + d;
                    __nv_bfloat16 h0 = __float2bfloat16_rn(v0);
                    __nv_bfloat16 h1 = __float2bfloat16_rn(v1);
                    __nv_bfloat16 l0 = __float2bfloat16_rn(v0 - __bfloat162float(h0));
                    __nv_bfloat16 l1 = __float2bfloat16_rn(v1 - __bfloat162float(h1));
                    ushort2 uh; uh.x = __bfloat16_as_ushort(h0); uh.y = __bfloat16_as_ushort(h1);
                    ushort2 ul; ul.x = __bfloat16_as_ushort(l0); ul.y = __bfloat16_as_ushort(l1);
                    *(ushort2*)&((unsigned short*)C0)[idx] = uh;
                    *(ushort2*)&((unsigned short*)C1)[idx] = ul;
                } else if (MODE == 2) {
                    const int bb = m >> 10, s = m & 1023, hh = n >> 6, d = n & 63;
                    const size_t idx = ((size_t)(bb * Hc + hh) * Dk + d) * Sc + s;
                    ((__half*)C0)[idx] = __float2half_rn(v0);
                    ((__half*)C0)[idx + Sc] = __float2half_rn(v1);
                } else {
                    const size_t idx = (size_t)m * 1024 + n;
                    float2 r = *(const float2*)&residual[idx];
                    float2 v; v.x = v0 + r.x; v.y = v1 + r.y;
                    *(float2*)&((float*)C0)[idx] = v;
                }
            }
        }
    }
}

// ===========================================================================
// scores kernel: S = Q.K^T (bf16 split, K=64), mask fused.
// R6 known-good: 256 threads, warp grid 4x2. grid (8 ntile, 8 mtile, 64 bh).
// ===========================================================================
#define SC_SMEM_SZ (4 * GT_TILEB)   // 73728

__global__ __launch_bounds__(256, 1)
void scores_kernel(const int* __restrict__ mask, float* __restrict__ S)
{
    extern __shared__ char smem[];
    const uint32_t sb = smem_to_u32(smem);
    const int tid = threadIdx.x;
    const int wid = tid >> 5, lane = tid & 31;
    const int wm = wid & 3, wn = wid >> 2;
    const int bh = blockIdx.z, b = bh >> 4;
    const int m0 = blockIdx.y * 128, n0 = blockIdx.x * 128;

    const size_t base = (size_t)bh * (Sc * Dk);
    const int crow = tid >> 1;
    const int chalf = tid & 1;
    const unsigned short* gsrc[4] = {
        g_Qh + base + (size_t)(m0 + crow) * 64 + chalf * 32,
        g_Ql + base + (size_t)(m0 + crow) * 64 + chalf * 32,
        g_Kh + base + (size_t)(n0 + crow) * 64 + chalf * 32,
        g_Kl + base + (size_t)(n0 + crow) * 64 + chalf * 32};
    const uint32_t srow = crow * (GT_ROW * 2) + chalf * 64;

#pragma unroll
    for (int tile = 0; tile < 4; tile++) {
        uint32_t s = sb + tile * GT_TILEB + srow;
#pragma unroll
        for (int i = 0; i < 4; i++)
            CP_ASYNC16(s + i * 16, gsrc[tile] + i * 8);
    }
    CP_COMMIT();

    float acc[2][8][4];
#pragma unroll
    for (int mt = 0; mt < 2; mt++)
#pragma unroll
        for (int nt = 0; nt < 8; nt++)
#pragma unroll
            for (int j = 0; j < 4; j++) acc[mt][nt][j] = 0.f;

    const int lg = lane >> 3, lr = lane & 7;
    const int rowoff = (lg & 1) * 8 + lr;
    const uint32_t kquad = (lg >> 1) * 16;

    CP_WAIT0();
    __syncthreads();

#pragma unroll
    for (int ks = 0; ks < 4; ks++) {
        const uint32_t kb = ks * 32 + kquad;
        uint32_t ah[2][4], al[2][4];
#pragma unroll
        for (int mt = 0; mt < 2; mt++) {
            uint32_t r = (wm * 32 + mt * 16 + rowoff) * (GT_ROW * 2) + kb;
            LDMATRIX_X4(ah[mt][0], ah[mt][1], ah[mt][2], ah[mt][3], sb + r);
            LDMATRIX_X4(al[mt][0], al[mt][1], al[mt][2], al[mt][3],
                        sb + GT_TILEB + r);
        }
        uint32_t bhf[8][2], blf[8][2];
#pragma unroll
        for (int p = 0; p < 4; p++) {
            uint32_t r = (wn * 64 + p * 16 + rowoff) * (GT_ROW * 2) + kb;
            LDMATRIX_X4(bhf[2 * p][0], bhf[2 * p + 1][0],
                        bhf[2 * p][1], bhf[2 * p + 1][1],
                        sb + 2 * GT_TILEB + r);
            LDMATRIX_X4(blf[2 * p][0], blf[2 * p + 1][0],
                        blf[2 * p][1], blf[2 * p + 1][1],
                        sb + 3 * GT_TILEB + r);
        }
#pragma unroll
        for (int mt = 0; mt < 2; mt++)
#pragma unroll
            for (int nt = 0; nt < 8; nt++) {
                MMA16816(acc[mt][nt], ah[mt], bhf[nt]);
                MMA16816(acc[mt][nt], ah[mt], blf[nt]);
                MMA16816(acc[mt][nt], al[mt], bhf[nt]);
            }
    }

    // epilogue: mask + store fp32 scores
    const int erow = lane >> 2;
    const int ecol = (lane & 3) * 2;
    float* Sb = S + (size_t)bh * Sc * Sc;
#pragma unroll
    for (int mt = 0; mt < 2; mt++) {
#pragma unroll
        for (int nt = 0; nt < 8; nt++) {
            const int n = n0 + wn * 64 + nt * 8 + ecol;
            const bool mk0 = (mask[b * Sc + n] == 0);
            const bool mk1 = (mask[b * Sc + n + 1] == 0);
#pragma unroll
            for (int half = 0; half < 2; half++) {
                const int m = m0 + wm * 32 + mt * 16 + erow + half * 8;
                float2 v;
                v.x = mk0 ? -1e9f : acc[mt][nt][half * 2 + 0];
                v.y = mk1 ? -1e9f : acc[mt][nt][half * 2 + 1];
                *(float2*)&Sb[(size_t)m * Sc + n] = v;
            }
        }
    }
}

// ===========================================================================
// FUSED softmax + ctx kernel.
// Block = 32 q-rows of one (b,h). 256 threads, 2 CTAs/SM.
// Phase 1: softmax on raw scores in gmem (in-place -> fp32 attn output),
//          fp16 probs parked in smem (row stride 2064B, ldmatrix-clean).
// Phase 2: ctx = P(smem) . V(gmem, cp.async double-buffered) via fp16 MMA,
//          32x64 output -> bf16 hi/lo split.
// grid (32 qtile, 64 bh).
// ===========================================================================
#define FX_PROWB 2064                          // 1024 halfs + 8 pad (16B shift/row)
#define FX_PBYTES (32 * FX_PROWB)              // 66048
#define FX_VROWB 144
#define FX_VTILEB (64 * FX_VROWB)              // 9216
#define FX_SMEM (FX_PBYTES + 2 * FX_VTILEB)    // 84480

__global__ __launch_bounds__(256, 2)
void softmax_ctx_kernel(float* __restrict__ S,
                        unsigned short* __restrict__ Chi,
                        unsigned short* __restrict__ Clo)
{
    extern __shared__ char smem[];
    const uint32_t sb = smem_to_u32(smem);
    const uint32_t sbV = sb + FX_PBYTES;
    const int tid = threadIdx.x;
    const int wid = tid >> 5, lane = tid & 31;
    const int bh = blockIdx.y, b = bh >> 4, h = bh & 15;
    const int m0 = blockIdx.x * 32;

    float* Sb = S + ((size_t)bh * Sc + m0) * Sc;
    const __half* Vb = g_VT + (size_t)bh * (Dk * Sc);

    // V tile loader: 64 rows(d) x 64 halfs(k), 2 threads/row on first 128 thr
    auto loadV = [&](int stg, int kt) {
        if (tid < 128) {
            const int brow = tid >> 1, bhalf = tid & 1;
            const __half* gbp = Vb + (size_t)brow * 1024 + kt * 64 + bhalf * 32;
            uint32_t sB = sbV + stg * FX_VTILEB + brow * FX_VROWB + bhalf * 64;
#pragma unroll
            for (int i = 0; i < 4; i++)
                CP_ASYNC16(sB + i * 16, gbp + i * 8);
        }
        CP_COMMIT();
    };

    // prefetch V tile 0 (independent of P)
    loadV(0, 0);

    // ---- phase 1: softmax, one warp handles 4 rows ----
#pragma unroll
    for (int r4 = 0; r4 < 4; r4++) {
        const int row = wid * 4 + r4;
        float* rp = Sb + (size_t)row * Sc;
        float4 v[8];
        float mx = -3.4e38f;
#pragma unroll
        for (int i = 0; i < 8; i++) {
            v[i] = *(const float4*)&rp[lane * 4 + i * 128];
            mx = fmaxf(mx, fmaxf(fmaxf(v[i].x, v[i].y), fmaxf(v[i].z, v[i].w)));
        }
#pragma unroll
        for (int o = 16; o; o >>= 1) mx = fmaxf(mx, __shfl_xor_sync(~0u, mx, o));
        float sum = 0.f;
#pragma unroll
        for (int i = 0; i < 8; i++) {
            v[i].x = expf(v[i].x - mx); v[i].y = expf(v[i].y - mx);
            v[i].z = expf(v[i].z - mx); v[i].w = expf(v[i].w - mx);
            sum += (v[i].x + v[i].y) + (v[i].z + v[i].w);
        }
#pragma unroll
        for (int o = 16; o; o >>= 1) sum += __shfl_xor_sync(~0u, sum, o);
        const float inv = 1.f / sum;
        const uint32_t srow = sb + row * FX_PROWB;
#pragma unroll
        for (int i = 0; i < 8; i++) {
            float4 p;
            p.x = v[i].x * inv; p.y = v[i].y * inv;
            p.z = v[i].z * inv; p.w = v[i].w * inv;
            *(float4*)&rp[lane * 4 + i * 128] = p;
            __half2 h0 = __floats2half2_rn(p.x, p.y);
            __half2 h1 = __floats2half2_rn(p.z, p.w);
            asm volatile("st.shared.v2.b32 [%0], {%1, %2};"
                :: "r"(srow + (lane * 4 + i * 128) * 2),
                   "r"(*(uint32_t*)&h0), "r"(*(uint32_t*)&h1) : "memory");
        }
    }
    __syncthreads();     // P smem complete

    // ---- phase 2: ctx = P . V ----
    const int wm = wid & 1, wn = wid >> 1;    // 2(m) x 4(n) warp grid
    float acc[2][4];
#pragma unroll
    for (int nt = 0; nt < 2; nt++)
#pragma unroll
        for (int j = 0; j < 4; j++) acc[nt][j] = 0.f;

    const int lg = lane >> 3, lr = lane & 7;
    const int rowoff = (lg & 1) * 8 + lr;
    const uint32_t kquad = (lg >> 1) * 16;

    CP_WAIT0();          // V tile 0 ready
    __syncthreads();

    for (int t = 0; t < 16; t++) {
        const int buf = t & 1;
        if (t + 1 < 16) loadV(buf ^ 1, t + 1);

        const uint32_t sV = sbV + buf * FX_VTILEB;
#pragma unroll
        for (int ks = 0; ks < 4; ks++) {
            const uint32_t kb = ks * 32 + kquad;
            uint32_t af[4];
            {
                uint32_t r = sb + (wm * 16 + rowoff) * FX_PROWB + t * 128 + kb;
                LDMATRIX_X4(af[0], af[1], af[2], af[3], r);
            }
            uint32_t bf[2][2];
            {
                uint32_t r = sV + (wn * 16 + rowoff) * FX_VROWB + kb;
                LDMATRIX_X4(bf[0][0], bf[1][0], bf[0][1], bf[1][1], r);
            }
            MMA16816F16(acc[0], af, bf[0]);
            MMA16816F16(acc[1], af, bf[1]);
        }
        if (t + 1 < 16) CP_WAIT0();
        __syncthreads();
    }

    // ---- epilogue: bf16 hi/lo split -> g_ch/g_cl ----
    const int erow = lane >> 2;
    const int ecol = (lane & 3) * 2;
#pragma unroll
    for (int nt = 0; nt < 2; nt++) {
        const int d = wn * 16 + nt * 8 + ecol;
#pragma unroll
        for (int half = 0; half < 2; half++) {
            const int q = m0 + wm * 16 + erow + half * 8;
            float v0 = acc[nt][half * 2 + 0];
            float v1 = acc[nt][half * 2 + 1];
            __nv_bfloat16 h0 = __float2bfloat16_rn(v0);
            __nv_bfloat16 h1 = __float2bfloat16_rn(v1);
            __nv_bfloat16 l0 = __float2bfloat16_rn(v0 - __bfloat162float(h0));
            __nv_bfloat16 l1 = __float2bfloat16_rn(v1 - __bfloat162float(h1));
            const size_t idx = ((size_t)(b * Sc) + q) * 1024 + h * Dk + d;
            ushort2 uh; uh.x = __bfloat16_as_ushort(h0); uh.y = __bfloat16_as_ushort(h1);
            ushort2 ul; ul.x = __bfloat16_as_ushort(l0); ul.y = __bfloat16_as_ushort(l1);
            *(ushort2*)&Chi[idx] = uh;
            *(ushort2*)&Clo[idx] = ul;
        }
    }
}

// ===========================================================================
// LayerNorm
// ===========================================================================
__global__ __launch_bounds__(256) void ln_kernel(
    const float* __restrict__ X, const float* __restrict__ gamma,
    const float* __restrict__ beta, float* __restrict__ out)
{
    __shared__ float red1[8];
    __shared__ float red2[8];
    const int row = blockIdx.x;
    const int tid = threadIdx.x;
    const float* x = X + (size_t)row * 1024;

    float v[4];
    float s = 0.f;
#pragma unroll
    for (int i = 0; i < 4; i++) { v[i] = x[tid + i * 256]; s += v[i]; }
#pragma unroll
    for (int o = 16; o; o >>= 1) s += __shfl_xor_sync(~0u, s, o);
    if ((tid & 31) == 0) red1[tid >> 5] = s;
    __syncthreads();
    if (tid < 32) {
        float t = (tid < 8) ? red1[tid] : 0.f;
#pragma unroll
        for (int o = 4; o; o >>= 1) t += __shfl_xor_sync(~0u, t, o);
        if (tid == 0) red1[0] = t;
    }
    __syncthreads();
    const float mu = red1[0] * (1.f / 1024.f);

    float ss = 0.f;
#pragma unroll
    for (int i = 0; i < 4; i++) { float d = v[i] - mu; ss += d * d; }
#pragma unroll
    for (int o = 16; o; o >>= 1) ss += __shfl_xor_sync(~0u, ss, o);
    if ((tid & 31) == 0) red2[tid >> 5] = ss;
    __syncthreads();
    if (tid < 32) {
        float t = (tid < 8) ? red2[tid] : 0.f;
#pragma unroll
        for (int o = 4; o; o >>= 1) t += __shfl_xor_sync(~0u, t, o);
        if (tid == 0) red2[0] = t;
    }
    __syncthreads();
    const float var = red2[0] * (1.f / 1024.f);
    const float rs = rsqrtf(var + 1e-5f);

#pragma unroll
    for (int i = 0; i < 4; i++) {
        const int c = tid + i * 256;
        out[(size_t)row * 1024 + c] = (v[i] - mu) * rs * gamma[c] + beta[c];
    }
}

// ===========================================================================
// Launch
// ===========================================================================
extern "C" void kernel_launch(void* const* d_in, const int* in_sizes, int n_in,
                              void* d_out, int out_size)
{
    const float* memory = (const float*)d_in[0];
    const float* dec    = (const float*)d_in[1];
    const int*   mask   = (const int*)d_in[2];
    const float* Wq = (const float*)d_in[3];
    const float* bq = (const float*)d_in[4];
    const float* Wk = (const float*)d_in[5];
    const float* bk = (const float*)d_in[6];
    const float* Wv = (const float*)d_in[7];
    const float* bv = (const float*)d_in[8];
    const float* Wo = (const float*)d_in[9];
    const float* bo = (const float*)d_in[10];
    const float* gamma = (const float*)d_in[11];
    const float* beta  = (const float*)d_in[12];

    float* out  = (float*)d_out;
    float* attn = out + (size_t)Bc * Sc * Dm;

    void *pX, *pmh, *pml, *pdh, *pdl, *pch, *pcl;
    cudaGetSymbolAddress(&pX, g_X);
    cudaGetSymbolAddress(&pmh, g_mh); cudaGetSymbolAddress(&pml, g_ml);
    cudaGetSymbolAddress(&pdh, g_dh); cudaGetSymbolAddress(&pdl, g_dl);
    cudaGetSymbolAddress(&pch, g_ch); cudaGetSymbolAddress(&pcl, g_cl);
    void *pqh, *pql, *pkh, *pkl, *pvh, *pvl, *poh, *pol;
    cudaGetSymbolAddress(&pqh, g_WqTh); cudaGetSymbolAddress(&pql, g_WqTl);
    cudaGetSymbolAddress(&pkh, g_WkTh); cudaGetSymbolAddress(&pkl, g_WkTl);
    cudaGetSymbolAddress(&pvh, g_WvTh); cudaGetSymbolAddress(&pvl, g_WvTl);
    cudaGetSymbolAddress(&poh, g_WoTh); cudaGetSymbolAddress(&pol, g_WoTl);
    void *pQh, *pQl, *pKh, *pKl, *pVT;
    cudaGetSymbolAddress(&pQh, g_Qh); cudaGetSymbolAddress(&pQl, g_Ql);
    cudaGetSymbolAddress(&pKh, g_Kh); cudaGetSymbolAddress(&pKl, g_Kl);
    cudaGetSymbolAddress(&pVT, g_VT);

    const int NACT4 = Bc * Sc * Dm / 4;

    // ---- prep (2 launches) ----
    SplitArgs sa;
    sa.src[0] = memory; sa.hi[0] = (unsigned short*)pmh; sa.lo[0] = (unsigned short*)pml;
    sa.src[1] = dec;    sa.hi[1] = (unsigned short*)pdh; sa.lo[1] = (unsigned short*)pdl;
    split2_kernel<<<dim3(NACT4 / 256, 2), 256>>>(sa, NACT4);

    TSArgs ta;
    ta.W[0] = Wq; ta.hi[0] = (unsigned short*)pqh; ta.lo[0] = (unsigned short*)pql;
    ta.W[1] = Wk; ta.hi[1] = (unsigned short*)pkh; ta.lo[1] = (unsigned short*)pkl;
    ta.W[2] = Wv; ta.hi[2] = (unsigned short*)pvh; ta.lo[2] = (unsigned short*)pvl;
    ta.W[3] = Wo; ta.hi[3] = (unsigned short*)poh; ta.lo[3] = (unsigned short*)pol;
    transsplit4_kernel<<<dim3(16, 16, 4), 256>>>(ta);

    // ---- projections (R6 known-good config) ----
    cudaFuncSetAttribute(gemm_mma<0>, cudaFuncAttributeMaxDynamicSharedMemorySize, GT_SMEM_SZ);
    cudaFuncSetAttribute(gemm_mma<1>, cudaFuncAttributeMaxDynamicSharedMemorySize, GT_SMEM_SZ);
    cudaFuncSetAttribute(gemm_mma<2>, cudaFuncAttributeMaxDynamicSharedMemorySize, GT_SMEM_SZ);
    const dim3 gg(8, 32), gt(256);
    gemm_mma<0><<<gg, gt, GT_SMEM_SZ>>>((unsigned short*)pmh, (unsigned short*)pml,
                                        (unsigned short*)pqh, (unsigned short*)pql,
                                        bq, nullptr, pQh, pQl, 0.125f);
    gemm_mma<0><<<gg, gt, GT_SMEM_SZ>>>((unsigned short*)pmh, (unsigned short*)pml,
                                        (unsigned short*)pkh, (unsigned short*)pkl,
                                        bk, nullptr, pKh, pKl, 1.0f);
    gemm_mma<2><<<gg, gt, GT_SMEM_SZ>>>((unsigned short*)pdh, (unsigned short*)pdl,
                                        (unsigned short*)pvh, (unsigned short*)pvl,
                                        bv, nullptr, pVT, nullptr, 1.0f);

    // ---- attention: scores -> fused softmax+ctx ----
    cudaFuncSetAttribute(scores_kernel, cudaFuncAttributeMaxDynamicSharedMemorySize, SC_SMEM_SZ);
    scores_kernel<<<dim3(8, 8, Bc * Hc), 256, SC_SMEM_SZ>>>(mask, attn);

    cudaFuncSetAttribute(softmax_ctx_kernel, cudaFuncAttributeMaxDynamicSharedMemorySize, FX_SMEM);
    softmax_ctx_kernel<<<dim3(32, Bc * Hc), 256, FX_SMEM>>>(attn,
                                                            (unsigned short*)pch,
                                                            (unsigned short*)pcl);

    // ---- output projection + residual, then LayerNorm ----
    gemm_mma<1><<<gg, gt, GT_SMEM_SZ>>>((unsigned short*)pch, (unsigned short*)pcl,
                                        (unsigned short*)poh, (unsigned short*)pol,
                                        bo, memory, pX, nullptr, 1.0f);
    ln_kernel<<<Bc * Sc, 256>>>((const float*)pX, gamma, beta, out);
}